// round 13
// baseline (speedup 1.0000x reference)
#include <cuda_runtime.h>
#include <cuda_bf16.h>
#include <math.h>
#include <stdint.h>

#define BB 2
#define NN 10000
#define EE 160000
#define DD 128
#define DIN 5
#define NLAYERS 4
#define BN (BB*NN)
#define NEGS 0.2f
#define EPSF 1e-5f
#define TM 128
#define NT_TILES ((BN + TM - 1) / TM)   // 157
#define SPAD 136                         // bf16 elems per padded smem row (272B)

// ---------------- scratch (device globals) -----------------------------------
__device__ float g_h[BN*DD];
__device__ float g_P[BN*DD];
__device__ float g_Q[BN*DD];
__device__ float g_aggr[BN*DD];
__device__ int   g_deg[NN];
__device__ int   g_row_off[NN+1];
__device__ int   g_cur[NN];
__device__ int   g_csr_col[EE];
__device__ float2 g_csr_ea[EE];
__device__ float g_gs[BB*DD];
__device__ float g_gate[BB*DD];
__device__ float g_W2u[NLAYERS*DD*DD];
__device__ float g_b2u[NLAYERS*DD];
__device__ int   g_done = 0;

__device__ __forceinline__ float lrelu(float x){ return x > 0.f ? x : NEGS*x; }

__device__ __forceinline__ uint32_t smem_u32(const void* p){
  uint32_t a;
  asm("{ .reg .u64 t; cvta.to.shared.u64 t, %1; cvt.u32.u64 %0, t; }" : "=r"(a) : "l"(p));
  return a;
}
__device__ __forceinline__ void bsplit(float x, __nv_bfloat16& h, __nv_bfloat16& l){
  h = __float2bfloat16(x);
  l = __float2bfloat16(x - __bfloat162float(h));
}
#define LDSM4(r0,r1,r2,r3,addr) \
  asm volatile("ldmatrix.sync.aligned.m8n8.x4.shared.b16 {%0,%1,%2,%3}, [%4];" \
    : "=r"(r0), "=r"(r1), "=r"(r2), "=r"(r3) : "r"(addr))
#define MMA16816(d, a0,a1,a2,a3, b0,b1) \
  asm volatile("mma.sync.aligned.m16n8k16.row.col.f32.bf16.bf16.f32 " \
    "{%0,%1,%2,%3}, {%4,%5,%6,%7}, {%8,%9}, {%0,%1,%2,%3};" \
    : "+f"((d)[0]), "+f"((d)[1]), "+f"((d)[2]), "+f"((d)[3]) \
    : "r"(a0), "r"(a1), "r"(a2), "r"(a3), "r"(b0), "r"(b1))

// ---------------- encoder ----------------------------------------------------
__global__ void k_encoder(const float* __restrict__ x, const float* __restrict__ W,
                          const float* __restrict__ b){
  int bn = blockIdx.x; int d = threadIdx.x;
  float acc = b[d];
  #pragma unroll
  for (int i = 0; i < DIN; i++) acc += x[bn*DIN + i] * W[i*DD + d];
  g_h[(size_t)bn*DD + d] = acc;
}

__global__ void k_ginit(){
  const int t = threadIdx.x;
  g_gate[t] = 1.f;
  g_gs[t] = 0.f;
}

// ---------------- CSR build --------------------------------------------------
__global__ void k_deg(const int* __restrict__ ei){
  int e = blockIdx.x*blockDim.x + threadIdx.x;
  if (e < EE) atomicAdd(&g_deg[ei[e]], 1);
}

// warp-shuffle scan: 1024 threads, 10 elems each, 2 barriers total
__global__ void k_scan(){
  __shared__ int wsum[32];
  const int t = threadIdx.x, lane = t & 31, wid = t >> 5;
  const int base = t*10;
  int local[10];
  int s = 0;
  #pragma unroll
  for (int j = 0; j < 10; j++){
    int idx = base + j;
    int v = (idx < NN) ? g_deg[idx] : 0;
    local[j] = s; s += v;
  }
  int inc = s;
  #pragma unroll
  for (int o = 1; o < 32; o <<= 1){
    int v = __shfl_up_sync(0xffffffffu, inc, o);
    if (lane >= o) inc += v;
  }
  if (lane == 31) wsum[wid] = inc;
  __syncthreads();
  if (wid == 0){
    int v = wsum[lane];
    int wi = v;
    #pragma unroll
    for (int o = 1; o < 32; o <<= 1){
      int u = __shfl_up_sync(0xffffffffu, wi, o);
      if (lane >= o) wi += u;
    }
    wsum[lane] = wi - v;   // exclusive warp offset
  }
  __syncthreads();
  const int prefix = wsum[wid] + (inc - s);
  #pragma unroll
  for (int j = 0; j < 10; j++){
    int idx = base + j;
    if (idx < NN){ g_row_off[idx] = prefix + local[j]; g_cur[idx] = prefix + local[j]; }
  }
  if (t == 0) g_row_off[NN] = EE;
}

__global__ void k_scatter(const int* __restrict__ ei, const float* __restrict__ ea){
  int e = blockIdx.x*blockDim.x + threadIdx.x;
  if (e >= EE) return;
  int r = ei[e];
  int pos = atomicAdd(&g_cur[r], 1);
  g_csr_col[pos] = ei[EE + e];
  g_csr_ea[pos] = make_float2(ea[2*e], ea[2*e+1]);
}

// ---------------- precompute W2u = W2 @ uW_bot, b2u = b2 @ uW_bot ------------
__global__ void k_prew2(const float* __restrict__ W2, const float* __restrict__ b2,
                        const float* __restrict__ uW){
  const int l = blockIdx.x, i = blockIdx.y, d = threadIdx.x;
  __shared__ float srow[DD];
  if (i < DD) srow[d] = W2[(size_t)l*DD*DD + i*DD + d];
  else        srow[d] = b2[l*DD + d];
  __syncthreads();
  const float* ub = uW + (size_t)l*256*DD + (size_t)DD*DD;
  float acc = 0.f;
  #pragma unroll 8
  for (int k = 0; k < DD; k++) acc += srow[k] * ub[k*DD + d];
  if (i < DD) g_W2u[(size_t)l*DD*DD + i*DD + d] = acc;
  else        g_b2u[l*DD + d] = acc;
}

// ======== HMMA GEMM 1: P = (h*gate)@WA, Q = (h*gate)@WB ======================
__global__ __launch_bounds__(256,1) void k_mmaPQ(
    const float* __restrict__ h, const float* __restrict__ WA,
    const float* __restrict__ WB, float* __restrict__ P, float* __restrict__ Q){
  extern __shared__ __nv_bfloat16 sm_[];
  __nv_bfloat16* Ah  = sm_;
  __nv_bfloat16* Al  = Ah  + 128*SPAD;
  __nv_bfloat16* Bah = Al  + 128*SPAD;
  __nv_bfloat16* Bal = Bah + 128*SPAD;
  __nv_bfloat16* Bbh = Bal + 128*SPAD;
  __nv_bfloat16* Bbl = Bbh + 128*SPAD;
  const int t = threadIdx.x, w = t >> 5, l = t & 31;
  for (int idx = t; idx < DD*DD; idx += 256){
    int k = idx >> 7, n = idx & 127;
    __nv_bfloat16 hh, ll;
    bsplit(WA[idx], hh, ll);
    Bah[n*SPAD + k] = hh; Bal[n*SPAD + k] = ll;
    bsplit(WB[idx], hh, ll);
    Bbh[n*SPAD + k] = hh; Bbl[n*SPAD + k] = ll;
  }
  __syncthreads();
  const int m0 = w * 16;
  const int arow = (l & 7) + ((l >> 3) & 1)*8, acol = ((l >> 4) & 1)*8;
  const int brow = (l & 7) + ((l >> 4) & 1)*8, bcol = ((l >> 3) & 1)*8;
  const uint32_t uAh = smem_u32(Ah) + ((m0 + arow)*SPAD + acol)*2;
  const uint32_t uAl = smem_u32(Al) + ((m0 + arow)*SPAD + acol)*2;
  const uint32_t uB[2][2] = {
    { smem_u32(Bah) + (brow*SPAD + bcol)*2, smem_u32(Bal) + (brow*SPAD + bcol)*2 },
    { smem_u32(Bbh) + (brow*SPAD + bcol)*2, smem_u32(Bbl) + (brow*SPAD + bcol)*2 } };
  for (int tile = blockIdx.x; tile < NT_TILES; tile += gridDim.x){
    const int node0 = tile * TM;
    for (int idx = t; idx < TM*64; idx += 256){
      int r = idx >> 6, k2 = (idx & 63) * 2;
      int node = node0 + r;
      float2 x = make_float2(0.f, 0.f);
      if (node < BN){
        x = *(const float2*)(h + (size_t)node*DD + k2);
        const int gb = (node < NN) ? 0 : DD;
        x.x *= g_gate[gb + k2]; x.y *= g_gate[gb + k2 + 1];
      }
      __nv_bfloat16 h0,l0,h1,l1;
      bsplit(x.x, h0, l0); bsplit(x.y, h1, l1);
      *(__nv_bfloat162*)(Ah + r*SPAD + k2) = __halves2bfloat162(h0, h1);
      *(__nv_bfloat162*)(Al + r*SPAD + k2) = __halves2bfloat162(l0, l1);
    }
    __syncthreads();
    #pragma unroll
    for (int out = 0; out < 2; out++){
      float acc[64];
      #pragma unroll
      for (int i = 0; i < 64; i++) acc[i] = 0.f;
      #pragma unroll
      for (int ks = 0; ks < 8; ks++){
        const uint32_t ko = ks * 32;
        uint32_t a0,a1,a2,a3, e0,e1,e2,e3;
        LDSM4(a0,a1,a2,a3, uAh + ko);
        LDSM4(e0,e1,e2,e3, uAl + ko);
        #pragma unroll
        for (int nt2 = 0; nt2 < 8; nt2++){
          const uint32_t no = nt2 * (16*SPAD*2);
          uint32_t bh0,bh1,bh2,bh3, bl0,bl1,bl2,bl3;
          LDSM4(bh0,bh1,bh2,bh3, uB[out][0] + no + ko);
          LDSM4(bl0,bl1,bl2,bl3, uB[out][1] + no + ko);
          float* d0 = acc + (nt2*2+0)*4;
          float* d1 = acc + (nt2*2+1)*4;
          MMA16816(d0, a0,a1,a2,a3, bh0,bh1);
          MMA16816(d0, a0,a1,a2,a3, bl0,bl1);
          MMA16816(d0, e0,e1,e2,e3, bh0,bh1);
          MMA16816(d1, a0,a1,a2,a3, bh2,bh3);
          MMA16816(d1, a0,a1,a2,a3, bl2,bl3);
          MMA16816(d1, e0,e1,e2,e3, bh2,bh3);
        }
      }
      float* Out = out ? Q : P;
      const int r0 = m0 + (l >> 2);
      const int n0v = node0 + r0, n1v = n0v + 8;
      #pragma unroll
      for (int nt = 0; nt < 16; nt++){
        const int col = nt*8 + 2*(l & 3);
        if (n0v < BN) *(float2*)(Out + (size_t)n0v*DD + col) = make_float2(acc[nt*4+0], acc[nt*4+1]);
        if (n1v < BN) *(float2*)(Out + (size_t)n1v*DD + col) = make_float2(acc[nt*4+2], acc[nt*4+3]);
      }
    }
    __syncthreads();
  }
}

// ======== HMMA GEMM 2: h = h*gate + LN(lrelu((h*gate)@uW_top + aggr@W2u + deg*b2u + ub))
__global__ __launch_bounds__(256,1) void k_mmaUP(
    const float* __restrict__ aggr, const float* __restrict__ uW,
    const float* __restrict__ W2u, const float* __restrict__ b2u,
    const float* __restrict__ ub, const float* __restrict__ lg,
    const float* __restrict__ lb){
  extern __shared__ float smf_[];
  float* sVec = smf_;    // ub[128], b2u[128], lg[128], lb[128], gate[256]
  __nv_bfloat16* Ah  = (__nv_bfloat16*)(smf_ + 768);
  __nv_bfloat16* Al  = Ah  + 128*SPAD;
  __nv_bfloat16* B0h = Al  + 128*SPAD;
  __nv_bfloat16* B0l = B0h + 128*SPAD;
  __nv_bfloat16* B1h = B0l + 128*SPAD;
  __nv_bfloat16* B1l = B1h + 128*SPAD;
  const int t = threadIdx.x, w = t >> 5, l = t & 31;
  if (t < 128){
    sVec[t] = ub[t]; sVec[128 + t] = b2u[t];
    sVec[256 + t] = lg[t]; sVec[384 + t] = lb[t];
  }
  if (t < 256) sVec[512 + t] = g_gate[t];
  for (int idx = t; idx < DD*DD; idx += 256){
    int k = idx >> 7, n = idx & 127;
    __nv_bfloat16 hh, ll;
    bsplit(uW[idx], hh, ll);
    B0h[n*SPAD + k] = hh; B0l[n*SPAD + k] = ll;
    bsplit(W2u[idx], hh, ll);
    B1h[n*SPAD + k] = hh; B1l[n*SPAD + k] = ll;
  }
  __syncthreads();
  const int m0 = w * 16;
  const int arow = (l & 7) + ((l >> 3) & 1)*8, acol = ((l >> 4) & 1)*8;
  const int brow = (l & 7) + ((l >> 4) & 1)*8, bcol = ((l >> 3) & 1)*8;
  const uint32_t uAh = smem_u32(Ah) + ((m0 + arow)*SPAD + acol)*2;
  const uint32_t uAl = smem_u32(Al) + ((m0 + arow)*SPAD + acol)*2;
  const uint32_t uB[2][2] = {
    { smem_u32(B0h) + (brow*SPAD + bcol)*2, smem_u32(B0l) + (brow*SPAD + bcol)*2 },
    { smem_u32(B1h) + (brow*SPAD + bcol)*2, smem_u32(B1l) + (brow*SPAD + bcol)*2 } };
  for (int tile = blockIdx.x; tile < NT_TILES; tile += gridDim.x){
    const int node0 = tile * TM;
    float acc[64];
    #pragma unroll
    for (int i = 0; i < 64; i++) acc[i] = 0.f;
    #pragma unroll
    for (int chunk = 0; chunk < 2; chunk++){
      const float* src = chunk ? aggr : g_h;
      for (int idx = t; idx < TM*64; idx += 256){
        int r = idx >> 6, k2 = (idx & 63) * 2;
        int node = node0 + r;
        float2 x = make_float2(0.f, 0.f);
        if (node < BN){
          x = *(const float2*)(src + (size_t)node*DD + k2);
          if (chunk == 0){
            const int gb = 512 + ((node < NN) ? 0 : DD);
            x.x *= sVec[gb + k2]; x.y *= sVec[gb + k2 + 1];
          }
        }
        __nv_bfloat16 h0,l0,h1,l1;
        bsplit(x.x, h0, l0); bsplit(x.y, h1, l1);
        *(__nv_bfloat162*)(Ah + r*SPAD + k2) = __halves2bfloat162(h0, h1);
        *(__nv_bfloat162*)(Al + r*SPAD + k2) = __halves2bfloat162(l0, l1);
      }
      __syncthreads();
      #pragma unroll
      for (int ks = 0; ks < 8; ks++){
        const uint32_t ko = ks * 32;
        uint32_t a0,a1,a2,a3, e0,e1,e2,e3;
        LDSM4(a0,a1,a2,a3, uAh + ko);
        LDSM4(e0,e1,e2,e3, uAl + ko);
        #pragma unroll
        for (int nt2 = 0; nt2 < 8; nt2++){
          const uint32_t no = nt2 * (16*SPAD*2);
          uint32_t bh0,bh1,bh2,bh3, bl0,bl1,bl2,bl3;
          LDSM4(bh0,bh1,bh2,bh3, uB[chunk][0] + no + ko);
          LDSM4(bl0,bl1,bl2,bl3, uB[chunk][1] + no + ko);
          float* d0 = acc + (nt2*2+0)*4;
          float* d1 = acc + (nt2*2+1)*4;
          MMA16816(d0, a0,a1,a2,a3, bh0,bh1);
          MMA16816(d0, a0,a1,a2,a3, bl0,bl1);
          MMA16816(d0, e0,e1,e2,e3, bh0,bh1);
          MMA16816(d1, a0,a1,a2,a3, bh2,bh3);
          MMA16816(d1, a0,a1,a2,a3, bl2,bl3);
          MMA16816(d1, e0,e1,e2,e3, bh2,bh3);
        }
      }
      __syncthreads();
    }
    const int r0 = m0 + (l >> 2);
    const int n0v = node0 + r0, n1v = n0v + 8;
    const float dg0 = (n0v < BN) ? (float)g_deg[n0v % NN] : 0.f;
    const float dg1 = (n1v < BN) ? (float)g_deg[n1v % NN] : 0.f;
    const int gb0 = 512 + ((n0v < NN) ? 0 : DD);
    const int gb1 = 512 + ((n1v < NN) ? 0 : DD);
    float s0 = 0.f, q0 = 0.f, s1 = 0.f, q1 = 0.f;
    #pragma unroll
    for (int nt = 0; nt < 16; nt++){
      const int col = nt*8 + 2*(l & 3);
      float v0 = lrelu(acc[nt*4+0] + sVec[col]   + dg0*sVec[128+col]);
      float v1 = lrelu(acc[nt*4+1] + sVec[col+1] + dg0*sVec[129+col]);
      float v2 = lrelu(acc[nt*4+2] + sVec[col]   + dg1*sVec[128+col]);
      float v3 = lrelu(acc[nt*4+3] + sVec[col+1] + dg1*sVec[129+col]);
      acc[nt*4+0] = v0; acc[nt*4+1] = v1; acc[nt*4+2] = v2; acc[nt*4+3] = v3;
      s0 += v0 + v1; q0 += v0*v0 + v1*v1;
      s1 += v2 + v3; q1 += v2*v2 + v3*v3;
    }
    #pragma unroll
    for (int o = 1; o < 4; o <<= 1){
      s0 += __shfl_xor_sync(0xffffffffu, s0, o);
      q0 += __shfl_xor_sync(0xffffffffu, q0, o);
      s1 += __shfl_xor_sync(0xffffffffu, s1, o);
      q1 += __shfl_xor_sync(0xffffffffu, q1, o);
    }
    const float mu0 = s0 * (1.f/DD);
    const float rs0 = rsqrtf(q0*(1.f/DD) - mu0*mu0 + EPSF);
    const float mu1 = s1 * (1.f/DD);
    const float rs1 = rsqrtf(q1*(1.f/DD) - mu1*mu1 + EPSF);
    #pragma unroll
    for (int nt = 0; nt < 16; nt++){
      const int col = nt*8 + 2*(l & 3);
      if (n0v < BN){
        float2 h2 = *(float2*)(g_h + (size_t)n0v*DD + col);
        h2.x = h2.x*sVec[gb0+col]   + (acc[nt*4+0] - mu0)*rs0*sVec[256+col]   + sVec[384+col];
        h2.y = h2.y*sVec[gb0+col+1] + (acc[nt*4+1] - mu0)*rs0*sVec[257+col]   + sVec[385+col];
        *(float2*)(g_h + (size_t)n0v*DD + col) = h2;
      }
      if (n1v < BN){
        float2 h2 = *(float2*)(g_h + (size_t)n1v*DD + col);
        h2.x = h2.x*sVec[gb1+col]   + (acc[nt*4+2] - mu1)*rs1*sVec[256+col]   + sVec[384+col];
        h2.y = h2.y*sVec[gb1+col+1] + (acc[nt*4+3] - mu1)*rs1*sVec[257+col]   + sVec[385+col];
        *(float2*)(g_h + (size_t)n1v*DD + col) = h2;
      }
    }
    __syncthreads();
  }
}

// ======== HMMA gc + fused gate (last-block-done) =============================
__global__ __launch_bounds__(256,1) void k_gcm(
    const float* __restrict__ h, const float* __restrict__ Wa,
    const float* __restrict__ ba,
    const float* __restrict__ Wb, const float* __restrict__ bb,
    const float* __restrict__ Wc, const float* __restrict__ bc){
  extern __shared__ __nv_bfloat16 sm_[];
  __nv_bfloat16* Ah = sm_;
  __nv_bfloat16* Al = Ah + 128*SPAD;
  __nv_bfloat16* Bh = Al + 128*SPAD;
  __nv_bfloat16* Bl = Bh + 128*SPAD;
  float* sBa  = (float*)(Bl + 128*SPAD);   // 128
  float* sRed = sBa + 128;                 // 2048
  __shared__ bool sLast;
  const int t = threadIdx.x, w = t >> 5, l = t & 31;
  for (int idx = t; idx < DD*DD; idx += 256){
    int k = idx >> 7, n = idx & 127;
    __nv_bfloat16 hh, ll;
    bsplit(Wa[idx], hh, ll);
    Bh[n*SPAD + k] = hh; Bl[n*SPAD + k] = ll;
  }
  if (t < 128) sBa[t] = ba[t];
  for (int i = t; i < 2048; i += 256) sRed[i] = 0.f;
  __syncthreads();
  const int m0 = w * 16;
  const int arow = (l & 7) + ((l >> 3) & 1)*8, acol = ((l >> 4) & 1)*8;
  const int brow = (l & 7) + ((l >> 4) & 1)*8, bcol = ((l >> 3) & 1)*8;
  const uint32_t uAh = smem_u32(Ah) + ((m0 + arow)*SPAD + acol)*2;
  const uint32_t uAl = smem_u32(Al) + ((m0 + arow)*SPAD + acol)*2;
  const uint32_t uBh = smem_u32(Bh) + (brow*SPAD + bcol)*2;
  const uint32_t uBl = smem_u32(Bl) + (brow*SPAD + bcol)*2;
  for (int tile = blockIdx.x; tile < NT_TILES; tile += gridDim.x){
    const int node0 = tile * TM;
    for (int idx = t; idx < TM*64; idx += 256){
      int r = idx >> 6, k2 = (idx & 63) * 2;
      int node = node0 + r;
      float2 x = (node < BN) ? *(const float2*)(h + (size_t)node*DD + k2)
                             : make_float2(0.f, 0.f);
      __nv_bfloat16 h0,l0,h1,l1;
      bsplit(x.x, h0, l0); bsplit(x.y, h1, l1);
      *(__nv_bfloat162*)(Ah + r*SPAD + k2) = __halves2bfloat162(h0, h1);
      *(__nv_bfloat162*)(Al + r*SPAD + k2) = __halves2bfloat162(l0, l1);
    }
    __syncthreads();
    const int r0 = m0 + (l >> 2);
    const int n0v = node0 + r0, n1v = n0v + 8;
    const bool a0ok = n0v < NN;
    const bool a1ok = n1v < NN;
    const bool b0ok = (n0v >= NN) && (n0v < BN);
    const bool b1ok = (n1v >= NN) && (n1v < BN);
    #pragma unroll
    for (int half = 0; half < 2; half++){
      float acc[32];
      #pragma unroll
      for (int i = 0; i < 32; i++) acc[i] = 0.f;
      #pragma unroll
      for (int ks = 0; ks < 8; ks++){
        const uint32_t ko = ks * 32;
        uint32_t a0,a1,a2,a3, e0,e1,e2,e3;
        LDSM4(a0,a1,a2,a3, uAh + ko);
        LDSM4(e0,e1,e2,e3, uAl + ko);
        #pragma unroll
        for (int j = 0; j < 4; j++){
          const uint32_t no = (uint32_t)(half*4 + j) * (16*SPAD*2);
          uint32_t bh0,bh1,bh2,bh3, bl0,bl1,bl2,bl3;
          LDSM4(bh0,bh1,bh2,bh3, uBh + no + ko);
          LDSM4(bl0,bl1,bl2,bl3, uBl + no + ko);
          float* d0 = acc + j*8;
          float* d1 = acc + j*8 + 4;
          MMA16816(d0, a0,a1,a2,a3, bh0,bh1);
          MMA16816(d0, a0,a1,a2,a3, bl0,bl1);
          MMA16816(d0, e0,e1,e2,e3, bh0,bh1);
          MMA16816(d1, a0,a1,a2,a3, bh2,bh3);
          MMA16816(d1, a0,a1,a2,a3, bl2,bl3);
          MMA16816(d1, e0,e1,e2,e3, bh2,bh3);
        }
      }
      #pragma unroll
      for (int j = 0; j < 4; j++){
        #pragma unroll
        for (int sub = 0; sub < 2; sub++){
          const int base = j*8 + sub*4;
          const int col = half*64 + j*16 + sub*8 + 2*(l & 3);
          const float z00 = lrelu(acc[base+0] + sBa[col]);
          const float z01 = lrelu(acc[base+1] + sBa[col+1]);
          const float z10 = lrelu(acc[base+2] + sBa[col]);
          const float z11 = lrelu(acc[base+3] + sBa[col+1]);
          float v0a = (a0ok ? z00 : 0.f) + (a1ok ? z10 : 0.f);
          float v0b = (a0ok ? z01 : 0.f) + (a1ok ? z11 : 0.f);
          float v1a = (b0ok ? z00 : 0.f) + (b1ok ? z10 : 0.f);
          float v1b = (b0ok ? z01 : 0.f) + (b1ok ? z11 : 0.f);
          #pragma unroll
          for (int o = 4; o < 32; o <<= 1){
            v0a += __shfl_xor_sync(0xffffffffu, v0a, o);
            v0b += __shfl_xor_sync(0xffffffffu, v0b, o);
            v1a += __shfl_xor_sync(0xffffffffu, v1a, o);
            v1b += __shfl_xor_sync(0xffffffffu, v1b, o);
          }
          if ((l >> 2) == j*2 + sub){
            float* slot = sRed + w*256;
            slot[col]         += v0a;
            slot[col + 1]     += v0b;
            slot[128 + col]   += v1a;
            slot[128 + col+1] += v1b;
          }
        }
      }
    }
    __syncthreads();
  }
  // block reduction -> global atomics
  if (t < 256){
    float s = 0.f;
    #pragma unroll
    for (int r = 0; r < 8; r++) s += sRed[r*256 + t];
    atomicAdd(&g_gs[t], s);
  }
  __threadfence();
  if (t == 0){
    int v = atomicAdd(&g_done, 1);
    sLast = (v == gridDim.x - 1);
  }
  __syncthreads();
  if (sLast){
    // gate = sigmoid(((gs/N)@Wb + bb) @ Wc + bc); reset gs, g_done
    float* zm = sRed;          // 256
    float* s2 = sRed + 256;    // 256
    const int b = t >> 7, d = t & 127;
    zm[t] = g_gs[t] * (1.f/NN);
    g_gs[t] = 0.f;
    __syncthreads();
    float acc = bb[d];
    #pragma unroll 8
    for (int k = 0; k < DD; k++) acc += zm[b*DD + k] * Wb[k*DD + d];
    s2[t] = acc;
    __syncthreads();
    float acc2 = bc[d];
    #pragma unroll 8
    for (int k = 0; k < DD; k++) acc2 += s2[b*DD + k] * Wc[k*DD + d];
    g_gate[t] = 1.f/(1.f + expf(-acc2));
    if (t == 0) g_done = 0;
  }
}

// -------- CSR aggregation: 2 edges x 2 batches per iteration (4 LN chains) ---
__global__ void k_aggregate(const float* __restrict__ P, const float* __restrict__ Q,
                            const float* __restrict__ W1c, const float* __restrict__ b1,
                            const float* __restrict__ lg, const float* __restrict__ lb,
                            float* __restrict__ aggr){
  const int n = (blockIdx.x*blockDim.x + threadIdx.x) >> 5;
  if (n >= NN) return;
  const int lane = threadIdx.x & 31;
  const int off = g_row_off[n], end = g_row_off[n+1];
  const float4* Qv = (const float4*)Q;
  const float4 p0 = ((const float4*)(P + (size_t)n*DD))[lane];
  const float4 p1 = ((const float4*)(P + (size_t)(NN + n)*DD))[lane];
  const float4 w0 = ((const float4*)W1c)[lane];
  const float4 w1 = ((const float4*)(W1c + DD))[lane];
  const float4 bv = ((const float4*)b1)[lane];
  const float4 gv = ((const float4*)lg)[lane];
  const float4 bt = ((const float4*)lb)[lane];
  float4 acc0 = make_float4(0,0,0,0), acc1 = make_float4(0,0,0,0);
  for (int i = off; i < end; i += 2){
    const int c0 = g_csr_col[i];
    const float2 e0 = g_csr_ea[i];
    const bool has1 = (i + 1 < end);
    const int c1 = has1 ? g_csr_col[i+1] : c0;
    const float2 e1 = has1 ? g_csr_ea[i+1] : make_float2(0.f, 0.f);
    const float4 q0a = Qv[(size_t)c0*32 + lane];
    const float4 q0b = Qv[(size_t)(NN + c0)*32 + lane];
    const float4 q1a = Qv[(size_t)c1*32 + lane];
    const float4 q1b = Qv[(size_t)(NN + c1)*32 + lane];
    const float f0x = e0.x*w0.x + e0.y*w1.x + bv.x;
    const float f0y = e0.x*w0.y + e0.y*w1.y + bv.y;
    const float f0z = e0.x*w0.z + e0.y*w1.z + bv.z;
    const float f0w = e0.x*w0.w + e0.y*w1.w + bv.w;
    const float f1x = e1.x*w0.x + e1.y*w1.x + bv.x;
    const float f1y = e1.x*w0.y + e1.y*w1.y + bv.y;
    const float f1z = e1.x*w0.z + e1.y*w1.z + bv.z;
    const float f1w = e1.x*w0.w + e1.y*w1.w + bv.w;
    // 4 chains: A = (e0,b0)  B = (e0,b1)  C = (e1,b0)  D = (e1,b1)
    const float A0 = lrelu(p0.x + q0a.x + f0x), A1 = lrelu(p0.y + q0a.y + f0y);
    const float A2 = lrelu(p0.z + q0a.z + f0z), A3 = lrelu(p0.w + q0a.w + f0w);
    const float B0 = lrelu(p1.x + q0b.x + f0x), B1 = lrelu(p1.y + q0b.y + f0y);
    const float B2 = lrelu(p1.z + q0b.z + f0z), B3 = lrelu(p1.w + q0b.w + f0w);
    const float C0 = lrelu(p0.x + q1a.x + f1x), C1 = lrelu(p0.y + q1a.y + f1y);
    const float C2 = lrelu(p0.z + q1a.z + f1z), C3 = lrelu(p0.w + q1a.w + f1w);
    const float D0 = lrelu(p1.x + q1b.x + f1x), D1 = lrelu(p1.y + q1b.y + f1y);
    const float D2 = lrelu(p1.z + q1b.z + f1z), D3 = lrelu(p1.w + q1b.w + f1w);
    float sA = A0+A1+A2+A3, uA = A0*A0+A1*A1+A2*A2+A3*A3;
    float sB = B0+B1+B2+B3, uB = B0*B0+B1*B1+B2*B2+B3*B3;
    float sC = C0+C1+C2+C3, uC = C0*C0+C1*C1+C2*C2+C3*C3;
    float sD = D0+D1+D2+D3, uD = D0*D0+D1*D1+D2*D2+D3*D3;
    #pragma unroll
    for (int o = 16; o; o >>= 1){
      sA += __shfl_xor_sync(0xffffffffu, sA, o);
      uA += __shfl_xor_sync(0xffffffffu, uA, o);
      sB += __shfl_xor_sync(0xffffffffu, sB, o);
      uB += __shfl_xor_sync(0xffffffffu, uB, o);
      sC += __shfl_xor_sync(0xffffffffu, sC, o);
      uC += __shfl_xor_sync(0xffffffffu, uC, o);
      sD += __shfl_xor_sync(0xffffffffu, sD, o);
      uD += __shfl_xor_sync(0xffffffffu, uD, o);
    }
    const float muA = sA*(1.f/DD), rsA = rsqrtf(uA*(1.f/DD) - muA*muA + EPSF);
    const float muB = sB*(1.f/DD), rsB = rsqrtf(uB*(1.f/DD) - muB*muB + EPSF);
    const float muC = sC*(1.f/DD), rsC = rsqrtf(uC*(1.f/DD) - muC*muC + EPSF);
    const float muD = sD*(1.f/DD), rsD = rsqrtf(uD*(1.f/DD) - muD*muD + EPSF);
    const float hf = has1 ? 1.f : 0.f;
    acc0.x += (A0 - muA)*rsA*gv.x + bt.x + hf*((C0 - muC)*rsC*gv.x + bt.x);
    acc0.y += (A1 - muA)*rsA*gv.y + bt.y + hf*((C1 - muC)*rsC*gv.y + bt.y);
    acc0.z += (A2 - muA)*rsA*gv.z + bt.z + hf*((C2 - muC)*rsC*gv.z + bt.z);
    acc0.w += (A3 - muA)*rsA*gv.w + bt.w + hf*((C3 - muC)*rsC*gv.w + bt.w);
    acc1.x += (B0 - muB)*rsB*gv.x + bt.x + hf*((D0 - muD)*rsD*gv.x + bt.x);
    acc1.y += (B1 - muB)*rsB*gv.y + bt.y + hf*((D1 - muD)*rsD*gv.y + bt.y);
    acc1.z += (B2 - muB)*rsB*gv.z + bt.z + hf*((D2 - muD)*rsD*gv.z + bt.z);
    acc1.w += (B3 - muB)*rsB*gv.w + bt.w + hf*((D3 - muD)*rsD*gv.w + bt.w);
  }
  ((float4*)(aggr + (size_t)n*DD))[lane] = acc0;
  ((float4*)(aggr + (size_t)(NN + n)*DD))[lane] = acc1;
}

__device__ __forceinline__ void fma4(float4& acc, const float4 x,
                                     const float4 w0, const float4 w1,
                                     const float4 w2, const float4 w3){
  acc.x += x.x*w0.x + x.y*w1.x + x.z*w2.x + x.w*w3.x;
  acc.y += x.x*w0.y + x.y*w1.y + x.z*w2.y + x.w*w3.y;
  acc.z += x.x*w0.z + x.y*w1.z + x.z*w2.z + x.w*w3.z;
  acc.w += x.x*w0.w + x.y*w1.w + x.z*w2.w + x.w*w3.w;
}

// ---------------- decoder (applies final gate at read) -----------------------
__global__ __launch_bounds__(256,1) void k_dec(const float* __restrict__ W1,
    const float* __restrict__ b1, const float* __restrict__ W2,
    const float* __restrict__ b2, float* __restrict__ out){
  extern __shared__ float sm[];
  float* sW1 = sm;
  float* sIn = sm + DD*68;
  float* sU  = sIn + 32*DD;
  float* sW2 = sU + 32*64;
  float* sGate = sW2 + 130;
  const int t = threadIdx.x;
  const int dG = t & 15, nG = t >> 4;
  const int d0 = dG << 2;
  const int lane = t & 31, warp = t >> 5;
  for (int i = t; i < DD*64; i += 256){
    int k = i >> 6, d = i & 63;
    sW1[k*68 + d] = W1[i];
  }
  if (t < 128) sW2[t] = W2[t];
  if (t < 2) sW2[128 + t] = b2[t];
  if (t < 256) sGate[t] = g_gate[t];
  const float4 b1v = ((const float4*)b1)[dG];
  __syncthreads();
  for (int tile = blockIdx.x; tile < BN/32; tile += gridDim.x){
    const int node0 = tile * 32;
    for (int i = t; i < 32*DD/4; i += 256){
      const int node = node0 + (i >> 5), k4 = (i & 31) * 4;
      const int gb = (node < NN) ? 0 : DD;
      float4 v = ((const float4*)(g_h + (size_t)node*DD))[i & 31];
      v.x *= sGate[gb + k4]; v.y *= sGate[gb + k4 + 1];
      v.z *= sGate[gb + k4 + 2]; v.w *= sGate[gb + k4 + 3];
      ((float4*)sIn)[i] = v;
    }
    __syncthreads();
    float4 acc[2];
    acc[0] = make_float4(0,0,0,0); acc[1] = make_float4(0,0,0,0);
    #pragma unroll 4
    for (int k = 0; k < DD; k += 4){
      const float4 w0 = *(const float4*)(sW1 + (k+0)*68 + d0);
      const float4 w1 = *(const float4*)(sW1 + (k+1)*68 + d0);
      const float4 w2 = *(const float4*)(sW1 + (k+2)*68 + d0);
      const float4 w3 = *(const float4*)(sW1 + (k+3)*68 + d0);
      #pragma unroll
      for (int j = 0; j < 2; j++){
        const float4 x = *(const float4*)(sIn + ((nG<<1)+j)*DD + k);
        fma4(acc[j], x, w0, w1, w2, w3);
      }
    }
    #pragma unroll
    for (int j = 0; j < 2; j++){
      float4 v = acc[j];
      v.x = lrelu(v.x + b1v.x); v.y = lrelu(v.y + b1v.y);
      v.z = lrelu(v.z + b1v.z); v.w = lrelu(v.w + b1v.w);
      *(float4*)(sU + ((nG<<1)+j)*64 + d0) = v;
    }
    __syncthreads();
    #pragma unroll
    for (int j = 0; j < 4; j++){
      const int nl = (warp<<2) + j;
      const float u0 = sU[nl*64 + lane];
      const float u1 = sU[nl*64 + lane + 32];
      float o0 = u0*sW2[lane*2]   + u1*sW2[(lane+32)*2];
      float o1 = u0*sW2[lane*2+1] + u1*sW2[(lane+32)*2+1];
      #pragma unroll
      for (int o = 16; o; o >>= 1){
        o0 += __shfl_xor_sync(0xffffffffu, o0, o);
        o1 += __shfl_xor_sync(0xffffffffu, o1, o);
      }
      if (lane == 0){
        out[(size_t)(node0 + nl)*2]     = o0 + sW2[128];
        out[(size_t)(node0 + nl)*2 + 1] = o1 + sW2[129];
      }
    }
    __syncthreads();
  }
}

// ---------------- host -------------------------------------------------------
extern "C" void kernel_launch(void* const* d_in, const int* in_sizes, int n_in,
                              void* d_out, int out_size){
  const float* x      = (const float*)d_in[0];
  const float* ea     = (const float*)d_in[1];
  const int*   ei     = (const int*)  d_in[2];
  const float* enc_W  = (const float*)d_in[3];
  const float* enc_b  = (const float*)d_in[4];
  const float* msg_W1 = (const float*)d_in[5];
  const float* msg_b1 = (const float*)d_in[6];
  const float* msg_lg = (const float*)d_in[7];
  const float* msg_lb = (const float*)d_in[8];
  const float* msg_W2 = (const float*)d_in[9];
  const float* msg_b2 = (const float*)d_in[10];
  const float* up_W   = (const float*)d_in[11];
  const float* up_b   = (const float*)d_in[12];
  const float* up_lg  = (const float*)d_in[13];
  const float* up_lb  = (const float*)d_in[14];
  const float* gc_Wa  = (const float*)d_in[15];
  const float* gc_ba  = (const float*)d_in[16];
  const float* gc_Wb  = (const float*)d_in[17];
  const float* gc_bb  = (const float*)d_in[18];
  const float* gc_Wc  = (const float*)d_in[19];
  const float* gc_bc  = (const float*)d_in[20];
  const float* dec_W1 = (const float*)d_in[21];
  const float* dec_b1 = (const float*)d_in[22];
  const float* dec_W2 = (const float*)d_in[23];
  const float* dec_b2 = (const float*)d_in[24];
  float* out = (float*)d_out;

  void *p_h, *p_P, *p_Q, *p_aggr, *p_deg, *p_W2u, *p_b2u;
  cudaGetSymbolAddress(&p_h, g_h);
  cudaGetSymbolAddress(&p_P, g_P);
  cudaGetSymbolAddress(&p_Q, g_Q);
  cudaGetSymbolAddress(&p_aggr, g_aggr);
  cudaGetSymbolAddress(&p_deg, g_deg);
  cudaGetSymbolAddress(&p_W2u, g_W2u);
  cudaGetSymbolAddress(&p_b2u, g_b2u);

  const int SM_MPQ = 6*128*SPAD*2;                        // 208896
  const int SM_MUP = 768*4 + 6*128*SPAD*2;                // 211968
  const int SM_GCM = 4*128*SPAD*2 + (128 + 2048)*4;       // 147968
  const int SM_DEC = (DD*68 + 32*DD + 32*64 + 130 + 256) * 4;
  cudaFuncSetAttribute(k_mmaPQ, cudaFuncAttributeMaxDynamicSharedMemorySize, SM_MPQ);
  cudaFuncSetAttribute(k_mmaUP, cudaFuncAttributeMaxDynamicSharedMemorySize, SM_MUP);
  cudaFuncSetAttribute(k_gcm,   cudaFuncAttributeMaxDynamicSharedMemorySize, SM_GCM);
  cudaFuncSetAttribute(k_dec,   cudaFuncAttributeMaxDynamicSharedMemorySize, SM_DEC);

  cudaMemsetAsync(p_deg, 0, NN*sizeof(int), 0);
  k_encoder<<<BN, DD>>>(x, enc_W, enc_b);
  k_ginit<<<1, 256>>>();
  k_deg<<<(EE + 255)/256, 256>>>(ei);
  k_scan<<<1, 1024>>>();
  k_scatter<<<(EE + 255)/256, 256>>>(ei, ea);
  { dim3 g(NLAYERS, DD+1); k_prew2<<<g, DD>>>(msg_W2, msg_b2, up_W); }

  for (int l = 0; l < NLAYERS; l++){
    const float* W1  = msg_W1 + (size_t)l*258*DD;
    const float* W1a = W1;
    const float* W1b = W1 + 128*DD;
    const float* W1c = W1 + 256*DD;
    const float* b1  = msg_b1 + l*DD;
    const float* mlg = msg_lg + l*DD;
    const float* mlb = msg_lb + l*DD;
    const float* uWl = up_W  + (size_t)l*256*DD;
    const float* ubl = up_b  + l*DD;
    const float* ulg = up_lg + l*DD;
    const float* ulb = up_lb + l*DD;
    const float* Wa  = gc_Wa + (size_t)l*DD*DD;
    const float* ba  = gc_ba + l*DD;
    const float* Wb  = gc_Wb + (size_t)l*DD*DD;
    const float* bbv = gc_bb + l*DD;
    const float* Wc  = gc_Wc + (size_t)l*DD*DD;
    const float* bc  = gc_bc + l*DD;
    const float* W2u = (const float*)p_W2u + (size_t)l*DD*DD;
    const float* b2u = (const float*)p_b2u + (size_t)l*DD;

    k_mmaPQ<<<148, 256, SM_MPQ>>>((const float*)p_h, W1a, W1b, (float*)p_P, (float*)p_Q);
    k_aggregate<<<(NN + 7)/8, 256>>>((const float*)p_P, (const float*)p_Q,
                                     W1c, b1, mlg, mlb, (float*)p_aggr);
    k_mmaUP<<<148, 256, SM_MUP>>>((const float*)p_aggr, uWl, W2u, b2u, ubl, ulg, ulb);
    k_gcm<<<148, 256, SM_GCM>>>((const float*)p_h, Wa, ba, Wb, bbv, Wc, bc);
  }

  k_dec<<<148, 256, SM_DEC>>>(dec_W1, dec_b1, dec_W2, dec_b2, out);
}

// round 14
// speedup vs baseline: 1.0482x; 1.0482x over previous
#include <cuda_runtime.h>
#include <cuda_bf16.h>
#include <math.h>
#include <stdint.h>

#define BB 2
#define NN 10000
#define EE 160000
#define DD 128
#define DIN 5
#define NLAYERS 4
#define BN (BB*NN)
#define NEGS 0.2f
#define EPSF 1e-5f
#define TM 128
#define NT_TILES ((BN + TM - 1) / TM)   // 157
#define SPAD 136                         // bf16 elems per padded smem row (272B)

// ---------------- scratch (device globals) -----------------------------------
__device__ float g_h[BN*DD];
__device__ float g_P[BN*DD];
__device__ float g_Q[BN*DD];
__device__ float g_aggr[BN*DD];
__device__ int   g_deg[NN];
__device__ int   g_row_off[NN+1];
__device__ int   g_cur[NN];
__device__ int   g_csr_col[EE];
__device__ float2 g_csr_ea[EE];
__device__ float g_gs[BB*DD];
__device__ float g_gate[BB*DD];
__device__ float g_W2u[NLAYERS*DD*DD];
__device__ float g_b2u[NLAYERS*DD];
__device__ int   g_done = 0;

__device__ __forceinline__ float lrelu(float x){ return x > 0.f ? x : NEGS*x; }

__device__ __forceinline__ uint32_t smem_u32(const void* p){
  uint32_t a;
  asm("{ .reg .u64 t; cvta.to.shared.u64 t, %1; cvt.u32.u64 %0, t; }" : "=r"(a) : "l"(p));
  return a;
}
__device__ __forceinline__ void bsplit(float x, __nv_bfloat16& h, __nv_bfloat16& l){
  h = __float2bfloat16(x);
  l = __float2bfloat16(x - __bfloat162float(h));
}
#define LDSM4(r0,r1,r2,r3,addr) \
  asm volatile("ldmatrix.sync.aligned.m8n8.x4.shared.b16 {%0,%1,%2,%3}, [%4];" \
    : "=r"(r0), "=r"(r1), "=r"(r2), "=r"(r3) : "r"(addr))
#define MMA16816(d, a0,a1,a2,a3, b0,b1) \
  asm volatile("mma.sync.aligned.m16n8k16.row.col.f32.bf16.bf16.f32 " \
    "{%0,%1,%2,%3}, {%4,%5,%6,%7}, {%8,%9}, {%0,%1,%2,%3};" \
    : "+f"((d)[0]), "+f"((d)[1]), "+f"((d)[2]), "+f"((d)[3]) \
    : "r"(a0), "r"(a1), "r"(a2), "r"(a3), "r"(b0), "r"(b1))

// ---------------- encoder ----------------------------------------------------
__global__ void k_encoder(const float* __restrict__ x, const float* __restrict__ W,
                          const float* __restrict__ b){
  int bn = blockIdx.x; int d = threadIdx.x;
  float acc = b[d];
  #pragma unroll
  for (int i = 0; i < DIN; i++) acc += x[bn*DIN + i] * W[i*DD + d];
  g_h[(size_t)bn*DD + d] = acc;
}

__global__ void k_ginit(){
  const int t = threadIdx.x;
  g_gate[t] = 1.f;
  g_gs[t] = 0.f;
}

// ---------------- CSR build --------------------------------------------------
__global__ void k_deg(const int* __restrict__ ei){
  int e = blockIdx.x*blockDim.x + threadIdx.x;
  if (e < EE) atomicAdd(&g_deg[ei[e]], 1);
}

// warp-shuffle scan: 1024 threads, 10 elems each, 2 barriers total
__global__ void k_scan(){
  __shared__ int wsum[32];
  const int t = threadIdx.x, lane = t & 31, wid = t >> 5;
  const int base = t*10;
  int local[10];
  int s = 0;
  #pragma unroll
  for (int j = 0; j < 10; j++){
    int idx = base + j;
    int v = (idx < NN) ? g_deg[idx] : 0;
    local[j] = s; s += v;
  }
  int inc = s;
  #pragma unroll
  for (int o = 1; o < 32; o <<= 1){
    int v = __shfl_up_sync(0xffffffffu, inc, o);
    if (lane >= o) inc += v;
  }
  if (lane == 31) wsum[wid] = inc;
  __syncthreads();
  if (wid == 0){
    int v = wsum[lane];
    int wi = v;
    #pragma unroll
    for (int o = 1; o < 32; o <<= 1){
      int u = __shfl_up_sync(0xffffffffu, wi, o);
      if (lane >= o) wi += u;
    }
    wsum[lane] = wi - v;   // exclusive warp offset
  }
  __syncthreads();
  const int prefix = wsum[wid] + (inc - s);
  #pragma unroll
  for (int j = 0; j < 10; j++){
    int idx = base + j;
    if (idx < NN){ g_row_off[idx] = prefix + local[j]; g_cur[idx] = prefix + local[j]; }
  }
  if (t == 0) g_row_off[NN] = EE;
}

__global__ void k_scatter(const int* __restrict__ ei, const float* __restrict__ ea){
  int e = blockIdx.x*blockDim.x + threadIdx.x;
  if (e >= EE) return;
  int r = ei[e];
  int pos = atomicAdd(&g_cur[r], 1);
  g_csr_col[pos] = ei[EE + e];
  g_csr_ea[pos] = make_float2(ea[2*e], ea[2*e+1]);
}

// ---------------- precompute W2u = W2 @ uW_bot, b2u = b2 @ uW_bot ------------
__global__ void k_prew2(const float* __restrict__ W2, const float* __restrict__ b2,
                        const float* __restrict__ uW){
  const int l = blockIdx.x, i = blockIdx.y, d = threadIdx.x;
  __shared__ float srow[DD];
  if (i < DD) srow[d] = W2[(size_t)l*DD*DD + i*DD + d];
  else        srow[d] = b2[l*DD + d];
  __syncthreads();
  const float* ub = uW + (size_t)l*256*DD + (size_t)DD*DD;
  float acc = 0.f;
  #pragma unroll 8
  for (int k = 0; k < DD; k++) acc += srow[k] * ub[k*DD + d];
  if (i < DD) g_W2u[(size_t)l*DD*DD + i*DD + d] = acc;
  else        g_b2u[l*DD + d] = acc;
}

// ======== HMMA GEMM 1: P = (h*gate)@WA, Q = (h*gate)@WB ======================
__global__ __launch_bounds__(256,1) void k_mmaPQ(
    const float* __restrict__ h, const float* __restrict__ WA,
    const float* __restrict__ WB, float* __restrict__ P, float* __restrict__ Q){
  extern __shared__ __nv_bfloat16 sm_[];
  __nv_bfloat16* Ah  = sm_;
  __nv_bfloat16* Al  = Ah  + 128*SPAD;
  __nv_bfloat16* Bah = Al  + 128*SPAD;
  __nv_bfloat16* Bal = Bah + 128*SPAD;
  __nv_bfloat16* Bbh = Bal + 128*SPAD;
  __nv_bfloat16* Bbl = Bbh + 128*SPAD;
  const int t = threadIdx.x, w = t >> 5, l = t & 31;
  for (int idx = t; idx < DD*DD; idx += 256){
    int k = idx >> 7, n = idx & 127;
    __nv_bfloat16 hh, ll;
    bsplit(WA[idx], hh, ll);
    Bah[n*SPAD + k] = hh; Bal[n*SPAD + k] = ll;
    bsplit(WB[idx], hh, ll);
    Bbh[n*SPAD + k] = hh; Bbl[n*SPAD + k] = ll;
  }
  __syncthreads();
  const int m0 = w * 16;
  const int arow = (l & 7) + ((l >> 3) & 1)*8, acol = ((l >> 4) & 1)*8;
  const int brow = (l & 7) + ((l >> 4) & 1)*8, bcol = ((l >> 3) & 1)*8;
  const uint32_t uAh = smem_u32(Ah) + ((m0 + arow)*SPAD + acol)*2;
  const uint32_t uAl = smem_u32(Al) + ((m0 + arow)*SPAD + acol)*2;
  const uint32_t uB[2][2] = {
    { smem_u32(Bah) + (brow*SPAD + bcol)*2, smem_u32(Bal) + (brow*SPAD + bcol)*2 },
    { smem_u32(Bbh) + (brow*SPAD + bcol)*2, smem_u32(Bbl) + (brow*SPAD + bcol)*2 } };
  for (int tile = blockIdx.x; tile < NT_TILES; tile += gridDim.x){
    const int node0 = tile * TM;
    for (int idx = t; idx < TM*64; idx += 256){
      int r = idx >> 6, k2 = (idx & 63) * 2;
      int node = node0 + r;
      float2 x = make_float2(0.f, 0.f);
      if (node < BN){
        x = *(const float2*)(h + (size_t)node*DD + k2);
        const int gb = (node < NN) ? 0 : DD;
        x.x *= g_gate[gb + k2]; x.y *= g_gate[gb + k2 + 1];
      }
      __nv_bfloat16 h0,l0,h1,l1;
      bsplit(x.x, h0, l0); bsplit(x.y, h1, l1);
      *(__nv_bfloat162*)(Ah + r*SPAD + k2) = __halves2bfloat162(h0, h1);
      *(__nv_bfloat162*)(Al + r*SPAD + k2) = __halves2bfloat162(l0, l1);
    }
    __syncthreads();
    #pragma unroll
    for (int out = 0; out < 2; out++){
      float acc[64];
      #pragma unroll
      for (int i = 0; i < 64; i++) acc[i] = 0.f;
      #pragma unroll
      for (int ks = 0; ks < 8; ks++){
        const uint32_t ko = ks * 32;
        uint32_t a0,a1,a2,a3, e0,e1,e2,e3;
        LDSM4(a0,a1,a2,a3, uAh + ko);
        LDSM4(e0,e1,e2,e3, uAl + ko);
        #pragma unroll
        for (int nt2 = 0; nt2 < 8; nt2++){
          const uint32_t no = nt2 * (16*SPAD*2);
          uint32_t bh0,bh1,bh2,bh3, bl0,bl1,bl2,bl3;
          LDSM4(bh0,bh1,bh2,bh3, uB[out][0] + no + ko);
          LDSM4(bl0,bl1,bl2,bl3, uB[out][1] + no + ko);
          float* d0 = acc + (nt2*2+0)*4;
          float* d1 = acc + (nt2*2+1)*4;
          MMA16816(d0, a0,a1,a2,a3, bh0,bh1);
          MMA16816(d0, a0,a1,a2,a3, bl0,bl1);
          MMA16816(d0, e0,e1,e2,e3, bh0,bh1);
          MMA16816(d1, a0,a1,a2,a3, bh2,bh3);
          MMA16816(d1, a0,a1,a2,a3, bl2,bl3);
          MMA16816(d1, e0,e1,e2,e3, bh2,bh3);
        }
      }
      float* Out = out ? Q : P;
      const int r0 = m0 + (l >> 2);
      const int n0v = node0 + r0, n1v = n0v + 8;
      #pragma unroll
      for (int nt = 0; nt < 16; nt++){
        const int col = nt*8 + 2*(l & 3);
        if (n0v < BN) *(float2*)(Out + (size_t)n0v*DD + col) = make_float2(acc[nt*4+0], acc[nt*4+1]);
        if (n1v < BN) *(float2*)(Out + (size_t)n1v*DD + col) = make_float2(acc[nt*4+2], acc[nt*4+3]);
      }
    }
    __syncthreads();
  }
}

// ======== HMMA GEMM 2: h = h*gate + LN(lrelu((h*gate)@uW_top + aggr@W2u + deg*b2u + ub))
__global__ __launch_bounds__(256,1) void k_mmaUP(
    const float* __restrict__ aggr, const float* __restrict__ uW,
    const float* __restrict__ W2u, const float* __restrict__ b2u,
    const float* __restrict__ ub, const float* __restrict__ lg,
    const float* __restrict__ lb){
  extern __shared__ float smf_[];
  float* sVec = smf_;    // ub[128], b2u[128], lg[128], lb[128], gate[256]
  __nv_bfloat16* Ah  = (__nv_bfloat16*)(smf_ + 768);
  __nv_bfloat16* Al  = Ah  + 128*SPAD;
  __nv_bfloat16* B0h = Al  + 128*SPAD;
  __nv_bfloat16* B0l = B0h + 128*SPAD;
  __nv_bfloat16* B1h = B0l + 128*SPAD;
  __nv_bfloat16* B1l = B1h + 128*SPAD;
  const int t = threadIdx.x, w = t >> 5, l = t & 31;
  if (t < 128){
    sVec[t] = ub[t]; sVec[128 + t] = b2u[t];
    sVec[256 + t] = lg[t]; sVec[384 + t] = lb[t];
  }
  if (t < 256) sVec[512 + t] = g_gate[t];
  for (int idx = t; idx < DD*DD; idx += 256){
    int k = idx >> 7, n = idx & 127;
    __nv_bfloat16 hh, ll;
    bsplit(uW[idx], hh, ll);
    B0h[n*SPAD + k] = hh; B0l[n*SPAD + k] = ll;
    bsplit(W2u[idx], hh, ll);
    B1h[n*SPAD + k] = hh; B1l[n*SPAD + k] = ll;
  }
  __syncthreads();
  const int m0 = w * 16;
  const int arow = (l & 7) + ((l >> 3) & 1)*8, acol = ((l >> 4) & 1)*8;
  const int brow = (l & 7) + ((l >> 4) & 1)*8, bcol = ((l >> 3) & 1)*8;
  const uint32_t uAh = smem_u32(Ah) + ((m0 + arow)*SPAD + acol)*2;
  const uint32_t uAl = smem_u32(Al) + ((m0 + arow)*SPAD + acol)*2;
  const uint32_t uB[2][2] = {
    { smem_u32(B0h) + (brow*SPAD + bcol)*2, smem_u32(B0l) + (brow*SPAD + bcol)*2 },
    { smem_u32(B1h) + (brow*SPAD + bcol)*2, smem_u32(B1l) + (brow*SPAD + bcol)*2 } };
  for (int tile = blockIdx.x; tile < NT_TILES; tile += gridDim.x){
    const int node0 = tile * TM;
    float acc[64];
    #pragma unroll
    for (int i = 0; i < 64; i++) acc[i] = 0.f;
    #pragma unroll
    for (int chunk = 0; chunk < 2; chunk++){
      const float* src = chunk ? aggr : g_h;
      for (int idx = t; idx < TM*64; idx += 256){
        int r = idx >> 6, k2 = (idx & 63) * 2;
        int node = node0 + r;
        float2 x = make_float2(0.f, 0.f);
        if (node < BN){
          x = *(const float2*)(src + (size_t)node*DD + k2);
          if (chunk == 0){
            const int gb = 512 + ((node < NN) ? 0 : DD);
            x.x *= sVec[gb + k2]; x.y *= sVec[gb + k2 + 1];
          }
        }
        __nv_bfloat16 h0,l0,h1,l1;
        bsplit(x.x, h0, l0); bsplit(x.y, h1, l1);
        *(__nv_bfloat162*)(Ah + r*SPAD + k2) = __halves2bfloat162(h0, h1);
        *(__nv_bfloat162*)(Al + r*SPAD + k2) = __halves2bfloat162(l0, l1);
      }
      __syncthreads();
      #pragma unroll
      for (int ks = 0; ks < 8; ks++){
        const uint32_t ko = ks * 32;
        uint32_t a0,a1,a2,a3, e0,e1,e2,e3;
        LDSM4(a0,a1,a2,a3, uAh + ko);
        LDSM4(e0,e1,e2,e3, uAl + ko);
        #pragma unroll
        for (int nt2 = 0; nt2 < 8; nt2++){
          const uint32_t no = nt2 * (16*SPAD*2);
          uint32_t bh0,bh1,bh2,bh3, bl0,bl1,bl2,bl3;
          LDSM4(bh0,bh1,bh2,bh3, uB[chunk][0] + no + ko);
          LDSM4(bl0,bl1,bl2,bl3, uB[chunk][1] + no + ko);
          float* d0 = acc + (nt2*2+0)*4;
          float* d1 = acc + (nt2*2+1)*4;
          MMA16816(d0, a0,a1,a2,a3, bh0,bh1);
          MMA16816(d0, a0,a1,a2,a3, bl0,bl1);
          MMA16816(d0, e0,e1,e2,e3, bh0,bh1);
          MMA16816(d1, a0,a1,a2,a3, bh2,bh3);
          MMA16816(d1, a0,a1,a2,a3, bl2,bl3);
          MMA16816(d1, e0,e1,e2,e3, bh2,bh3);
        }
      }
      __syncthreads();
    }
    const int r0 = m0 + (l >> 2);
    const int n0v = node0 + r0, n1v = n0v + 8;
    const float dg0 = (n0v < BN) ? (float)g_deg[n0v % NN] : 0.f;
    const float dg1 = (n1v < BN) ? (float)g_deg[n1v % NN] : 0.f;
    const int gb0 = 512 + ((n0v < NN) ? 0 : DD);
    const int gb1 = 512 + ((n1v < NN) ? 0 : DD);
    float s0 = 0.f, q0 = 0.f, s1 = 0.f, q1 = 0.f;
    #pragma unroll
    for (int nt = 0; nt < 16; nt++){
      const int col = nt*8 + 2*(l & 3);
      float v0 = lrelu(acc[nt*4+0] + sVec[col]   + dg0*sVec[128+col]);
      float v1 = lrelu(acc[nt*4+1] + sVec[col+1] + dg0*sVec[129+col]);
      float v2 = lrelu(acc[nt*4+2] + sVec[col]   + dg1*sVec[128+col]);
      float v3 = lrelu(acc[nt*4+3] + sVec[col+1] + dg1*sVec[129+col]);
      acc[nt*4+0] = v0; acc[nt*4+1] = v1; acc[nt*4+2] = v2; acc[nt*4+3] = v3;
      s0 += v0 + v1; q0 += v0*v0 + v1*v1;
      s1 += v2 + v3; q1 += v2*v2 + v3*v3;
    }
    #pragma unroll
    for (int o = 1; o < 4; o <<= 1){
      s0 += __shfl_xor_sync(0xffffffffu, s0, o);
      q0 += __shfl_xor_sync(0xffffffffu, q0, o);
      s1 += __shfl_xor_sync(0xffffffffu, s1, o);
      q1 += __shfl_xor_sync(0xffffffffu, q1, o);
    }
    const float mu0 = s0 * (1.f/DD);
    const float rs0 = rsqrtf(q0*(1.f/DD) - mu0*mu0 + EPSF);
    const float mu1 = s1 * (1.f/DD);
    const float rs1 = rsqrtf(q1*(1.f/DD) - mu1*mu1 + EPSF);
    #pragma unroll
    for (int nt = 0; nt < 16; nt++){
      const int col = nt*8 + 2*(l & 3);
      if (n0v < BN){
        float2 h2 = *(float2*)(g_h + (size_t)n0v*DD + col);
        h2.x = h2.x*sVec[gb0+col]   + (acc[nt*4+0] - mu0)*rs0*sVec[256+col]   + sVec[384+col];
        h2.y = h2.y*sVec[gb0+col+1] + (acc[nt*4+1] - mu0)*rs0*sVec[257+col]   + sVec[385+col];
        *(float2*)(g_h + (size_t)n0v*DD + col) = h2;
      }
      if (n1v < BN){
        float2 h2 = *(float2*)(g_h + (size_t)n1v*DD + col);
        h2.x = h2.x*sVec[gb1+col]   + (acc[nt*4+2] - mu1)*rs1*sVec[256+col]   + sVec[384+col];
        h2.y = h2.y*sVec[gb1+col+1] + (acc[nt*4+3] - mu1)*rs1*sVec[257+col]   + sVec[385+col];
        *(float2*)(g_h + (size_t)n1v*DD + col) = h2;
      }
    }
    __syncthreads();
  }
}

// ======== HMMA gc + fused gate (last-block-done) =============================
__global__ __launch_bounds__(256,1) void k_gcm(
    const float* __restrict__ h, const float* __restrict__ Wa,
    const float* __restrict__ ba,
    const float* __restrict__ Wb, const float* __restrict__ bb,
    const float* __restrict__ Wc, const float* __restrict__ bc){
  extern __shared__ __nv_bfloat16 sm_[];
  __nv_bfloat16* Ah = sm_;
  __nv_bfloat16* Al = Ah + 128*SPAD;
  __nv_bfloat16* Bh = Al + 128*SPAD;
  __nv_bfloat16* Bl = Bh + 128*SPAD;
  float* sBa  = (float*)(Bl + 128*SPAD);   // 128
  float* sRed = sBa + 128;                 // 2048
  __shared__ bool sLast;
  const int t = threadIdx.x, w = t >> 5, l = t & 31;
  for (int idx = t; idx < DD*DD; idx += 256){
    int k = idx >> 7, n = idx & 127;
    __nv_bfloat16 hh, ll;
    bsplit(Wa[idx], hh, ll);
    Bh[n*SPAD + k] = hh; Bl[n*SPAD + k] = ll;
  }
  if (t < 128) sBa[t] = ba[t];
  for (int i = t; i < 2048; i += 256) sRed[i] = 0.f;
  __syncthreads();
  const int m0 = w * 16;
  const int arow = (l & 7) + ((l >> 3) & 1)*8, acol = ((l >> 4) & 1)*8;
  const int brow = (l & 7) + ((l >> 4) & 1)*8, bcol = ((l >> 3) & 1)*8;
  const uint32_t uAh = smem_u32(Ah) + ((m0 + arow)*SPAD + acol)*2;
  const uint32_t uAl = smem_u32(Al) + ((m0 + arow)*SPAD + acol)*2;
  const uint32_t uBh = smem_u32(Bh) + (brow*SPAD + bcol)*2;
  const uint32_t uBl = smem_u32(Bl) + (brow*SPAD + bcol)*2;
  for (int tile = blockIdx.x; tile < NT_TILES; tile += gridDim.x){
    const int node0 = tile * TM;
    for (int idx = t; idx < TM*64; idx += 256){
      int r = idx >> 6, k2 = (idx & 63) * 2;
      int node = node0 + r;
      float2 x = (node < BN) ? *(const float2*)(h + (size_t)node*DD + k2)
                             : make_float2(0.f, 0.f);
      __nv_bfloat16 h0,l0,h1,l1;
      bsplit(x.x, h0, l0); bsplit(x.y, h1, l1);
      *(__nv_bfloat162*)(Ah + r*SPAD + k2) = __halves2bfloat162(h0, h1);
      *(__nv_bfloat162*)(Al + r*SPAD + k2) = __halves2bfloat162(l0, l1);
    }
    __syncthreads();
    const int r0 = m0 + (l >> 2);
    const int n0v = node0 + r0, n1v = n0v + 8;
    const bool a0ok = n0v < NN;
    const bool a1ok = n1v < NN;
    const bool b0ok = (n0v >= NN) && (n0v < BN);
    const bool b1ok = (n1v >= NN) && (n1v < BN);
    #pragma unroll
    for (int half = 0; half < 2; half++){
      float acc[32];
      #pragma unroll
      for (int i = 0; i < 32; i++) acc[i] = 0.f;
      #pragma unroll
      for (int ks = 0; ks < 8; ks++){
        const uint32_t ko = ks * 32;
        uint32_t a0,a1,a2,a3, e0,e1,e2,e3;
        LDSM4(a0,a1,a2,a3, uAh + ko);
        LDSM4(e0,e1,e2,e3, uAl + ko);
        #pragma unroll
        for (int j = 0; j < 4; j++){
          const uint32_t no = (uint32_t)(half*4 + j) * (16*SPAD*2);
          uint32_t bh0,bh1,bh2,bh3, bl0,bl1,bl2,bl3;
          LDSM4(bh0,bh1,bh2,bh3, uBh + no + ko);
          LDSM4(bl0,bl1,bl2,bl3, uBl + no + ko);
          float* d0 = acc + j*8;
          float* d1 = acc + j*8 + 4;
          MMA16816(d0, a0,a1,a2,a3, bh0,bh1);
          MMA16816(d0, a0,a1,a2,a3, bl0,bl1);
          MMA16816(d0, e0,e1,e2,e3, bh0,bh1);
          MMA16816(d1, a0,a1,a2,a3, bh2,bh3);
          MMA16816(d1, a0,a1,a2,a3, bl2,bl3);
          MMA16816(d1, e0,e1,e2,e3, bh2,bh3);
        }
      }
      #pragma unroll
      for (int j = 0; j < 4; j++){
        #pragma unroll
        for (int sub = 0; sub < 2; sub++){
          const int base = j*8 + sub*4;
          const int col = half*64 + j*16 + sub*8 + 2*(l & 3);
          const float z00 = lrelu(acc[base+0] + sBa[col]);
          const float z01 = lrelu(acc[base+1] + sBa[col+1]);
          const float z10 = lrelu(acc[base+2] + sBa[col]);
          const float z11 = lrelu(acc[base+3] + sBa[col+1]);
          float v0a = (a0ok ? z00 : 0.f) + (a1ok ? z10 : 0.f);
          float v0b = (a0ok ? z01 : 0.f) + (a1ok ? z11 : 0.f);
          float v1a = (b0ok ? z00 : 0.f) + (b1ok ? z10 : 0.f);
          float v1b = (b0ok ? z01 : 0.f) + (b1ok ? z11 : 0.f);
          #pragma unroll
          for (int o = 4; o < 32; o <<= 1){
            v0a += __shfl_xor_sync(0xffffffffu, v0a, o);
            v0b += __shfl_xor_sync(0xffffffffu, v0b, o);
            v1a += __shfl_xor_sync(0xffffffffu, v1a, o);
            v1b += __shfl_xor_sync(0xffffffffu, v1b, o);
          }
          if ((l >> 2) == j*2 + sub){
            float* slot = sRed + w*256;
            slot[col]         += v0a;
            slot[col + 1]     += v0b;
            slot[128 + col]   += v1a;
            slot[128 + col+1] += v1b;
          }
        }
      }
    }
    __syncthreads();
  }
  // block reduction -> global atomics
  if (t < 256){
    float s = 0.f;
    #pragma unroll
    for (int r = 0; r < 8; r++) s += sRed[r*256 + t];
    atomicAdd(&g_gs[t], s);
  }
  __threadfence();
  if (t == 0){
    int v = atomicAdd(&g_done, 1);
    sLast = (v == gridDim.x - 1);
  }
  __syncthreads();
  if (sLast){
    // gate = sigmoid(((gs/N)@Wb + bb) @ Wc + bc); reset gs, g_done
    float* zm = sRed;          // 256
    float* s2 = sRed + 256;    // 256
    const int b = t >> 7, d = t & 127;
    zm[t] = g_gs[t] * (1.f/NN);
    g_gs[t] = 0.f;
    __syncthreads();
    float acc = bb[d];
    #pragma unroll 8
    for (int k = 0; k < DD; k++) acc += zm[b*DD + k] * Wb[k*DD + d];
    s2[t] = acc;
    __syncthreads();
    float acc2 = bc[d];
    #pragma unroll 8
    for (int k = 0; k < DD; k++) acc2 += s2[b*DD + k] * Wc[k*DD + d];
    g_gate[t] = 1.f/(1.f + expf(-acc2));
    if (t == 0) g_done = 0;
  }
}

// -------- CSR aggregation: both batches per warp, software prefetch ----------
__global__ void k_aggregate(const float* __restrict__ P, const float* __restrict__ Q,
                            const float* __restrict__ W1c, const float* __restrict__ b1,
                            const float* __restrict__ lg, const float* __restrict__ lb,
                            float* __restrict__ aggr){
  const int n = (blockIdx.x*blockDim.x + threadIdx.x) >> 5;
  if (n >= NN) return;
  const int lane = threadIdx.x & 31;
  const int off = g_row_off[n], end = g_row_off[n+1];
  const float4* Qv = (const float4*)Q;
  const float4 p0 = ((const float4*)(P + (size_t)n*DD))[lane];
  const float4 p1 = ((const float4*)(P + (size_t)(NN + n)*DD))[lane];
  const float4 w0 = ((const float4*)W1c)[lane];
  const float4 w1 = ((const float4*)(W1c + DD))[lane];
  const float4 bv = ((const float4*)b1)[lane];
  const float4 gv = ((const float4*)lg)[lane];
  const float4 bt = ((const float4*)lb)[lane];
  float4 acc0 = make_float4(0,0,0,0), acc1 = make_float4(0,0,0,0);
  int ncol = 0; float2 nea = make_float2(0,0);
  float4 qa = make_float4(0,0,0,0), qb = make_float4(0,0,0,0);
  if (off < end){
    ncol = g_csr_col[off]; nea = g_csr_ea[off];
    qa = Qv[(size_t)ncol*32 + lane];
    qb = Qv[(size_t)(NN + ncol)*32 + lane];
  }
  for (int i = off; i < end; i++){
    const float4 q0c = qa, q1c = qb; const float2 ec = nea;
    if (i + 1 < end){
      ncol = g_csr_col[i+1]; nea = g_csr_ea[i+1];
      qa = Qv[(size_t)ncol*32 + lane];
      qb = Qv[(size_t)(NN + ncol)*32 + lane];
    }
    const float ex0 = ec.x*w0.x + ec.y*w1.x + bv.x;
    const float ex1 = ec.x*w0.y + ec.y*w1.y + bv.y;
    const float ex2 = ec.x*w0.z + ec.y*w1.z + bv.z;
    const float ex3 = ec.x*w0.w + ec.y*w1.w + bv.w;
    const float a0 = lrelu(p0.x + q0c.x + ex0);
    const float a1 = lrelu(p0.y + q0c.y + ex1);
    const float a2 = lrelu(p0.z + q0c.z + ex2);
    const float a3 = lrelu(p0.w + q0c.w + ex3);
    const float b0 = lrelu(p1.x + q1c.x + ex0);
    const float b1x = lrelu(p1.y + q1c.y + ex1);
    const float b2 = lrelu(p1.z + q1c.z + ex2);
    const float b3 = lrelu(p1.w + q1c.w + ex3);
    float s0  = a0 + a1 + a2 + a3;
    float u0  = a0*a0 + a1*a1 + a2*a2 + a3*a3;
    float s1  = b0 + b1x + b2 + b3;
    float u1  = b0*b0 + b1x*b1x + b2*b2 + b3*b3;
    #pragma unroll
    for (int o = 16; o; o >>= 1){
      s0 += __shfl_xor_sync(0xffffffffu, s0, o);
      u0 += __shfl_xor_sync(0xffffffffu, u0, o);
      s1 += __shfl_xor_sync(0xffffffffu, s1, o);
      u1 += __shfl_xor_sync(0xffffffffu, u1, o);
    }
    const float mu0 = s0 * (1.f/DD);
    const float rs0 = rsqrtf(u0*(1.f/DD) - mu0*mu0 + EPSF);
    const float mu1 = s1 * (1.f/DD);
    const float rs1 = rsqrtf(u1*(1.f/DD) - mu1*mu1 + EPSF);
    acc0.x += (a0 - mu0)*rs0*gv.x + bt.x;
    acc0.y += (a1 - mu0)*rs0*gv.y + bt.y;
    acc0.z += (a2 - mu0)*rs0*gv.z + bt.z;
    acc0.w += (a3 - mu0)*rs0*gv.w + bt.w;
    acc1.x += (b0  - mu1)*rs1*gv.x + bt.x;
    acc1.y += (b1x - mu1)*rs1*gv.y + bt.y;
    acc1.z += (b2  - mu1)*rs1*gv.z + bt.z;
    acc1.w += (b3  - mu1)*rs1*gv.w + bt.w;
  }
  ((float4*)(aggr + (size_t)n*DD))[lane] = acc0;
  ((float4*)(aggr + (size_t)(NN + n)*DD))[lane] = acc1;
}

__device__ __forceinline__ void fma4(float4& acc, const float4 x,
                                     const float4 w0, const float4 w1,
                                     const float4 w2, const float4 w3){
  acc.x += x.x*w0.x + x.y*w1.x + x.z*w2.x + x.w*w3.x;
  acc.y += x.x*w0.y + x.y*w1.y + x.z*w2.y + x.w*w3.y;
  acc.z += x.x*w0.z + x.y*w1.z + x.z*w2.z + x.w*w3.z;
  acc.w += x.x*w0.w + x.y*w1.w + x.z*w2.w + x.w*w3.w;
}

// ---------------- decoder (applies final gate at read) -----------------------
__global__ __launch_bounds__(256,1) void k_dec(const float* __restrict__ W1,
    const float* __restrict__ b1, const float* __restrict__ W2,
    const float* __restrict__ b2, float* __restrict__ out){
  extern __shared__ float sm[];
  float* sW1 = sm;
  float* sIn = sm + DD*68;
  float* sU  = sIn + 32*DD;
  float* sW2 = sU + 32*64;
  float* sGate = sW2 + 130;
  const int t = threadIdx.x;
  const int dG = t & 15, nG = t >> 4;
  const int d0 = dG << 2;
  const int lane = t & 31, warp = t >> 5;
  for (int i = t; i < DD*64; i += 256){
    int k = i >> 6, d = i & 63;
    sW1[k*68 + d] = W1[i];
  }
  if (t < 128) sW2[t] = W2[t];
  if (t < 2) sW2[128 + t] = b2[t];
  if (t < 256) sGate[t] = g_gate[t];
  const float4 b1v = ((const float4*)b1)[dG];
  __syncthreads();
  for (int tile = blockIdx.x; tile < BN/32; tile += gridDim.x){
    const int node0 = tile * 32;
    for (int i = t; i < 32*DD/4; i += 256){
      const int node = node0 + (i >> 5), k4 = (i & 31) * 4;
      const int gb = (node < NN) ? 0 : DD;
      float4 v = ((const float4*)(g_h + (size_t)node*DD))[i & 31];
      v.x *= sGate[gb + k4]; v.y *= sGate[gb + k4 + 1];
      v.z *= sGate[gb + k4 + 2]; v.w *= sGate[gb + k4 + 3];
      ((float4*)sIn)[i] = v;
    }
    __syncthreads();
    float4 acc[2];
    acc[0] = make_float4(0,0,0,0); acc[1] = make_float4(0,0,0,0);
    #pragma unroll 4
    for (int k = 0; k < DD; k += 4){
      const float4 w0 = *(const float4*)(sW1 + (k+0)*68 + d0);
      const float4 w1 = *(const float4*)(sW1 + (k+1)*68 + d0);
      const float4 w2 = *(const float4*)(sW1 + (k+2)*68 + d0);
      const float4 w3 = *(const float4*)(sW1 + (k+3)*68 + d0);
      #pragma unroll
      for (int j = 0; j < 2; j++){
        const float4 x = *(const float4*)(sIn + ((nG<<1)+j)*DD + k);
        fma4(acc[j], x, w0, w1, w2, w3);
      }
    }
    #pragma unroll
    for (int j = 0; j < 2; j++){
      float4 v = acc[j];
      v.x = lrelu(v.x + b1v.x); v.y = lrelu(v.y + b1v.y);
      v.z = lrelu(v.z + b1v.z); v.w = lrelu(v.w + b1v.w);
      *(float4*)(sU + ((nG<<1)+j)*64 + d0) = v;
    }
    __syncthreads();
    #pragma unroll
    for (int j = 0; j < 4; j++){
      const int nl = (warp<<2) + j;
      const float u0 = sU[nl*64 + lane];
      const float u1 = sU[nl*64 + lane + 32];
      float o0 = u0*sW2[lane*2]   + u1*sW2[(lane+32)*2];
      float o1 = u0*sW2[lane*2+1] + u1*sW2[(lane+32)*2+1];
      #pragma unroll
      for (int o = 16; o; o >>= 1){
        o0 += __shfl_xor_sync(0xffffffffu, o0, o);
        o1 += __shfl_xor_sync(0xffffffffu, o1, o);
      }
      if (lane == 0){
        out[(size_t)(node0 + nl)*2]     = o0 + sW2[128];
        out[(size_t)(node0 + nl)*2 + 1] = o1 + sW2[129];
      }
    }
    __syncthreads();
  }
}

// ---------------- host -------------------------------------------------------
extern "C" void kernel_launch(void* const* d_in, const int* in_sizes, int n_in,
                              void* d_out, int out_size){
  const float* x      = (const float*)d_in[0];
  const float* ea     = (const float*)d_in[1];
  const int*   ei     = (const int*)  d_in[2];
  const float* enc_W  = (const float*)d_in[3];
  const float* enc_b  = (const float*)d_in[4];
  const float* msg_W1 = (const float*)d_in[5];
  const float* msg_b1 = (const float*)d_in[6];
  const float* msg_lg = (const float*)d_in[7];
  const float* msg_lb = (const float*)d_in[8];
  const float* msg_W2 = (const float*)d_in[9];
  const float* msg_b2 = (const float*)d_in[10];
  const float* up_W   = (const float*)d_in[11];
  const float* up_b   = (const float*)d_in[12];
  const float* up_lg  = (const float*)d_in[13];
  const float* up_lb  = (const float*)d_in[14];
  const float* gc_Wa  = (const float*)d_in[15];
  const float* gc_ba  = (const float*)d_in[16];
  const float* gc_Wb  = (const float*)d_in[17];
  const float* gc_bb  = (const float*)d_in[18];
  const float* gc_Wc  = (const float*)d_in[19];
  const float* gc_bc  = (const float*)d_in[20];
  const float* dec_W1 = (const float*)d_in[21];
  const float* dec_b1 = (const float*)d_in[22];
  const float* dec_W2 = (const float*)d_in[23];
  const float* dec_b2 = (const float*)d_in[24];
  float* out = (float*)d_out;

  void *p_h, *p_P, *p_Q, *p_aggr, *p_deg, *p_W2u, *p_b2u;
  cudaGetSymbolAddress(&p_h, g_h);
  cudaGetSymbolAddress(&p_P, g_P);
  cudaGetSymbolAddress(&p_Q, g_Q);
  cudaGetSymbolAddress(&p_aggr, g_aggr);
  cudaGetSymbolAddress(&p_deg, g_deg);
  cudaGetSymbolAddress(&p_W2u, g_W2u);
  cudaGetSymbolAddress(&p_b2u, g_b2u);

  const int SM_MPQ = 6*128*SPAD*2;                        // 208896
  const int SM_MUP = 768*4 + 6*128*SPAD*2;                // 211968
  const int SM_GCM = 4*128*SPAD*2 + (128 + 2048)*4;       // 147968
  const int SM_DEC = (DD*68 + 32*DD + 32*64 + 130 + 256) * 4;
  cudaFuncSetAttribute(k_mmaPQ, cudaFuncAttributeMaxDynamicSharedMemorySize, SM_MPQ);
  cudaFuncSetAttribute(k_mmaUP, cudaFuncAttributeMaxDynamicSharedMemorySize, SM_MUP);
  cudaFuncSetAttribute(k_gcm,   cudaFuncAttributeMaxDynamicSharedMemorySize, SM_GCM);
  cudaFuncSetAttribute(k_dec,   cudaFuncAttributeMaxDynamicSharedMemorySize, SM_DEC);

  cudaMemsetAsync(p_deg, 0, NN*sizeof(int), 0);
  k_encoder<<<BN, DD>>>(x, enc_W, enc_b);
  k_ginit<<<1, 256>>>();
  k_deg<<<(EE + 255)/256, 256>>>(ei);
  k_scan<<<1, 1024>>>();
  k_scatter<<<(EE + 255)/256, 256>>>(ei, ea);
  { dim3 g(NLAYERS, DD+1); k_prew2<<<g, DD>>>(msg_W2, msg_b2, up_W); }

  for (int l = 0; l < NLAYERS; l++){
    const float* W1  = msg_W1 + (size_t)l*258*DD;
    const float* W1a = W1;
    const float* W1b = W1 + 128*DD;
    const float* W1c = W1 + 256*DD;
    const float* b1  = msg_b1 + l*DD;
    const float* mlg = msg_lg + l*DD;
    const float* mlb = msg_lb + l*DD;
    const float* uWl = up_W  + (size_t)l*256*DD;
    const float* ubl = up_b  + l*DD;
    const float* ulg = up_lg + l*DD;
    const float* ulb = up_lb + l*DD;
    const float* Wa  = gc_Wa + (size_t)l*DD*DD;
    const float* ba  = gc_ba + l*DD;
    const float* Wb  = gc_Wb + (size_t)l*DD*DD;
    const float* bbv = gc_bb + l*DD;
    const float* Wc  = gc_Wc + (size_t)l*DD*DD;
    const float* bc  = gc_bc + l*DD;
    const float* W2u = (const float*)p_W2u + (size_t)l*DD*DD;
    const float* b2u = (const float*)p_b2u + (size_t)l*DD;

    k_mmaPQ<<<148, 256, SM_MPQ>>>((const float*)p_h, W1a, W1b, (float*)p_P, (float*)p_Q);
    k_aggregate<<<(NN + 7)/8, 256>>>((const float*)p_P, (const float*)p_Q,
                                     W1c, b1, mlg, mlb, (float*)p_aggr);
    k_mmaUP<<<148, 256, SM_MUP>>>((const float*)p_aggr, uWl, W2u, b2u, ubl, ulg, ulb);
    k_gcm<<<148, 256, SM_GCM>>>((const float*)p_h, Wa, ba, Wb, bbv, Wc, bc);
  }

  k_dec<<<148, 256, SM_DEC>>>(dec_W1, dec_b1, dec_W2, dec_b2, out);
}

// round 15
// speedup vs baseline: 1.0545x; 1.0060x over previous
#include <cuda_runtime.h>
#include <cuda_bf16.h>
#include <math.h>
#include <stdint.h>

#define BB 2
#define NN 10000
#define EE 160000
#define DD 128
#define DIN 5
#define NLAYERS 4
#define BN (BB*NN)
#define NEGS 0.2f
#define EPSF 1e-5f
#define TM 128
#define NT_TILES ((BN + TM - 1) / TM)   // 157
#define SPAD 136                         // bf16 elems per padded smem row (272B)
#define WMAT (128*SPAD)                  // elems per split matrix buffer
#define WCPY (WMAT*2/16)                 // float4 per matrix buffer = 2176

// ---------------- scratch (device globals) -----------------------------------
__device__ float g_h[BN*DD];
__device__ float g_P[BN*DD];
__device__ float g_Q[BN*DD];
__device__ float g_aggr[BN*DD];
__device__ int   g_deg[NN];
__device__ int   g_row_off[NN+1];
__device__ int   g_cur[NN];
__device__ int   g_csr_col[EE];
__device__ float2 g_csr_ea[EE];
__device__ float g_gs[BB*DD];
__device__ float g_gate[BB*DD];
__device__ float g_W2u[NLAYERS*DD*DD];
__device__ float g_b2u[NLAYERS*DD];
__device__ __nv_bfloat16 g_wsp[(size_t)NLAYERS*5*2*WMAT];  // padded hi/lo splits
__device__ int   g_done = 0;

__device__ __forceinline__ float lrelu(float x){ return x > 0.f ? x : NEGS*x; }

__device__ __forceinline__ uint32_t smem_u32(const void* p){
  uint32_t a;
  asm("{ .reg .u64 t; cvta.to.shared.u64 t, %1; cvt.u32.u64 %0, t; }" : "=r"(a) : "l"(p));
  return a;
}
__device__ __forceinline__ void bsplit(float x, __nv_bfloat16& h, __nv_bfloat16& l){
  h = __float2bfloat16(x);
  l = __float2bfloat16(x - __bfloat162float(h));
}
#define LDSM4(r0,r1,r2,r3,addr) \
  asm volatile("ldmatrix.sync.aligned.m8n8.x4.shared.b16 {%0,%1,%2,%3}, [%4];" \
    : "=r"(r0), "=r"(r1), "=r"(r2), "=r"(r3) : "r"(addr))
#define MMA16816(d, a0,a1,a2,a3, b0,b1) \
  asm volatile("mma.sync.aligned.m16n8k16.row.col.f32.bf16.bf16.f32 " \
    "{%0,%1,%2,%3}, {%4,%5,%6,%7}, {%8,%9}, {%0,%1,%2,%3};" \
    : "+f"((d)[0]), "+f"((d)[1]), "+f"((d)[2]), "+f"((d)[3]) \
    : "r"(a0), "r"(a1), "r"(a2), "r"(a3), "r"(b0), "r"(b1))

// stage a 128x128 float tile (optionally gated) into padded bf16 hi/lo smem
__device__ __forceinline__ void stage_tile(const float* __restrict__ src, int node0,
    __nv_bfloat16* Ah, __nv_bfloat16* Al, const float* gate, int t){
  for (int idx = t; idx < TM*32; idx += 256){
    const int r = idx >> 5, k4 = (idx & 31) << 2;
    const int node = node0 + r;
    float4 x = make_float4(0.f, 0.f, 0.f, 0.f);
    if (node < BN){
      x = *(const float4*)(src + (size_t)node*DD + k4);
      if (gate){
        const float* gp = gate + ((node < NN) ? 0 : DD) + k4;
        x.x *= gp[0]; x.y *= gp[1]; x.z *= gp[2]; x.w *= gp[3];
      }
    }
    __nv_bfloat16 h0,l0,h1,l1,h2,l2,h3,l3;
    bsplit(x.x,h0,l0); bsplit(x.y,h1,l1); bsplit(x.z,h2,l2); bsplit(x.w,h3,l3);
    __nv_bfloat16* pa = Ah + r*SPAD + k4;
    __nv_bfloat16* pl = Al + r*SPAD + k4;
    *(__nv_bfloat162*)(pa)     = __halves2bfloat162(h0,h1);
    *(__nv_bfloat162*)(pa + 2) = __halves2bfloat162(h2,h3);
    *(__nv_bfloat162*)(pl)     = __halves2bfloat162(l0,l1);
    *(__nv_bfloat162*)(pl + 2) = __halves2bfloat162(l2,l3);
  }
}

// ---------------- encoder ----------------------------------------------------
__global__ void k_encoder(const float* __restrict__ x, const float* __restrict__ W,
                          const float* __restrict__ b){
  int bn = blockIdx.x; int d = threadIdx.x;
  float acc = b[d];
  #pragma unroll
  for (int i = 0; i < DIN; i++) acc += x[bn*DIN + i] * W[i*DD + d];
  g_h[(size_t)bn*DD + d] = acc;
}

__global__ void k_ginit(){
  const int t = threadIdx.x;
  g_gate[t] = 1.f;
  g_gs[t] = 0.f;
}

// ---------------- CSR build --------------------------------------------------
__global__ void k_deg(const int* __restrict__ ei){
  int e = blockIdx.x*blockDim.x + threadIdx.x;
  if (e < EE) atomicAdd(&g_deg[ei[e]], 1);
}

__global__ void k_scan(){
  __shared__ int wsum[32];
  const int t = threadIdx.x, lane = t & 31, wid = t >> 5;
  const int base = t*10;
  int local[10];
  int s = 0;
  #pragma unroll
  for (int j = 0; j < 10; j++){
    int idx = base + j;
    int v = (idx < NN) ? g_deg[idx] : 0;
    local[j] = s; s += v;
  }
  int inc = s;
  #pragma unroll
  for (int o = 1; o < 32; o <<= 1){
    int v = __shfl_up_sync(0xffffffffu, inc, o);
    if (lane >= o) inc += v;
  }
  if (lane == 31) wsum[wid] = inc;
  __syncthreads();
  if (wid == 0){
    int v = wsum[lane];
    int wi = v;
    #pragma unroll
    for (int o = 1; o < 32; o <<= 1){
      int u = __shfl_up_sync(0xffffffffu, wi, o);
      if (lane >= o) wi += u;
    }
    wsum[lane] = wi - v;
  }
  __syncthreads();
  const int prefix = wsum[wid] + (inc - s);
  #pragma unroll
  for (int j = 0; j < 10; j++){
    int idx = base + j;
    if (idx < NN){ g_row_off[idx] = prefix + local[j]; g_cur[idx] = prefix + local[j]; }
  }
  if (t == 0) g_row_off[NN] = EE;
}

__global__ void k_scatter(const int* __restrict__ ei, const float* __restrict__ ea){
  int e = blockIdx.x*blockDim.x + threadIdx.x;
  if (e >= EE) return;
  int r = ei[e];
  int pos = atomicAdd(&g_cur[r], 1);
  g_csr_col[pos] = ei[EE + e];
  g_csr_ea[pos] = ((const float2*)ea)[e];
}

// ---------------- precompute W2u = W2 @ uW_bot, b2u = b2 @ uW_bot ------------
__global__ void k_prew2(const float* __restrict__ W2, const float* __restrict__ b2,
                        const float* __restrict__ uW){
  const int l = blockIdx.x, i = blockIdx.y, d = threadIdx.x;
  __shared__ float srow[DD];
  if (i < DD) srow[d] = W2[(size_t)l*DD*DD + i*DD + d];
  else        srow[d] = b2[l*DD + d];
  __syncthreads();
  const float* ub = uW + (size_t)l*256*DD + (size_t)DD*DD;
  float acc = 0.f;
  #pragma unroll 8
  for (int k = 0; k < DD; k++) acc += srow[k] * ub[k*DD + d];
  if (i < DD) g_W2u[(size_t)l*DD*DD + i*DD + d] = acc;
  else        g_b2u[l*DD + d] = acc;
}

// -------- presplit weights into padded bf16 hi/lo (transposed) ---------------
// matrices per layer: 0=W1a 1=W1b 2=uW_top 3=W2u 4=Wa
__global__ void k_presplit(const float* __restrict__ msg_W1,
                           const float* __restrict__ up_W,
                           const float* __restrict__ gc_Wa){
  const int l = blockIdx.x, m = blockIdx.y, t = threadIdx.x;
  const float* src;
  if      (m == 0) src = msg_W1 + (size_t)l*258*DD;
  else if (m == 1) src = msg_W1 + (size_t)l*258*DD + (size_t)128*DD;
  else if (m == 2) src = up_W   + (size_t)l*256*DD;
  else if (m == 3) src = g_W2u  + (size_t)l*DD*DD;
  else             src = gc_Wa  + (size_t)l*DD*DD;
  __nv_bfloat16* dh = g_wsp + ((size_t)(l*5 + m)*2 + 0)*WMAT;
  __nv_bfloat16* dl = g_wsp + ((size_t)(l*5 + m)*2 + 1)*WMAT;
  for (int idx = t; idx < DD*DD; idx += 256){
    const int k = idx >> 7, n = idx & 127;
    __nv_bfloat16 hh, ll;
    bsplit(src[idx], hh, ll);
    dh[n*SPAD + k] = hh;
    dl[n*SPAD + k] = ll;
  }
}

// ======== HMMA GEMM 1: P = (h*gate)@WA, Q = (h*gate)@WB ======================
__global__ __launch_bounds__(256,1) void k_mmaPQ(
    const float* __restrict__ h, int layer,
    float* __restrict__ P, float* __restrict__ Q){
  extern __shared__ __nv_bfloat16 sm_[];
  __nv_bfloat16* Ah  = sm_;
  __nv_bfloat16* Al  = Ah  + WMAT;
  __nv_bfloat16* Bah = Al  + WMAT;    // 4 contiguous matrix buffers follow
  __nv_bfloat16* Bbh = Bah + 2*WMAT;
  const int t = threadIdx.x, w = t >> 5, l = t & 31;
  { const float4* s4 = (const float4*)(g_wsp + (size_t)(layer*5)*2*WMAT);
    float4* d4 = (float4*)Bah;
    for (int i = t; i < 4*WCPY; i += 256) d4[i] = s4[i]; }
  __syncthreads();
  const int m0 = w * 16;
  const int arow = (l & 7) + ((l >> 3) & 1)*8, acol = ((l >> 4) & 1)*8;
  const int brow = (l & 7) + ((l >> 4) & 1)*8, bcol = ((l >> 3) & 1)*8;
  const uint32_t uAh = smem_u32(Ah) + ((m0 + arow)*SPAD + acol)*2;
  const uint32_t uAl = smem_u32(Al) + ((m0 + arow)*SPAD + acol)*2;
  const uint32_t uB[2][2] = {
    { smem_u32(Bah) + (brow*SPAD + bcol)*2, smem_u32(Bah + WMAT) + (brow*SPAD + bcol)*2 },
    { smem_u32(Bbh) + (brow*SPAD + bcol)*2, smem_u32(Bbh + WMAT) + (brow*SPAD + bcol)*2 } };
  for (int tile = blockIdx.x; tile < NT_TILES; tile += gridDim.x){
    const int node0 = tile * TM;
    stage_tile(h, node0, Ah, Al, g_gate, t);
    __syncthreads();
    #pragma unroll
    for (int out = 0; out < 2; out++){
      float acc[64];
      #pragma unroll
      for (int i = 0; i < 64; i++) acc[i] = 0.f;
      #pragma unroll
      for (int ks = 0; ks < 8; ks++){
        const uint32_t ko = ks * 32;
        uint32_t a0,a1,a2,a3, e0,e1,e2,e3;
        LDSM4(a0,a1,a2,a3, uAh + ko);
        LDSM4(e0,e1,e2,e3, uAl + ko);
        #pragma unroll
        for (int nt2 = 0; nt2 < 8; nt2++){
          const uint32_t no = nt2 * (16*SPAD*2);
          uint32_t bh0,bh1,bh2,bh3, bl0,bl1,bl2,bl3;
          LDSM4(bh0,bh1,bh2,bh3, uB[out][0] + no + ko);
          LDSM4(bl0,bl1,bl2,bl3, uB[out][1] + no + ko);
          float* d0 = acc + (nt2*2+0)*4;
          float* d1 = acc + (nt2*2+1)*4;
          MMA16816(d0, a0,a1,a2,a3, bh0,bh1);
          MMA16816(d0, a0,a1,a2,a3, bl0,bl1);
          MMA16816(d0, e0,e1,e2,e3, bh0,bh1);
          MMA16816(d1, a0,a1,a2,a3, bh2,bh3);
          MMA16816(d1, a0,a1,a2,a3, bl2,bl3);
          MMA16816(d1, e0,e1,e2,e3, bh2,bh3);
        }
      }
      float* Out = out ? Q : P;
      const int r0 = m0 + (l >> 2);
      const int n0v = node0 + r0, n1v = n0v + 8;
      #pragma unroll
      for (int nt = 0; nt < 16; nt++){
        const int col = nt*8 + 2*(l & 3);
        if (n0v < BN) *(float2*)(Out + (size_t)n0v*DD + col) = make_float2(acc[nt*4+0], acc[nt*4+1]);
        if (n1v < BN) *(float2*)(Out + (size_t)n1v*DD + col) = make_float2(acc[nt*4+2], acc[nt*4+3]);
      }
    }
    __syncthreads();
  }
}

// ======== HMMA GEMM 2: h = h*gate + LN(lrelu((h*gate)@uW_top + aggr@W2u + deg*b2u + ub))
__global__ __launch_bounds__(256,1) void k_mmaUP(
    const float* __restrict__ aggr, int layer,
    const float* __restrict__ b2u, const float* __restrict__ ub,
    const float* __restrict__ lg, const float* __restrict__ lb){
  extern __shared__ float smf_[];
  float* sVec = smf_;    // ub[128], b2u[128], lg[128], lb[128], gate[256]
  __nv_bfloat16* Ah  = (__nv_bfloat16*)(smf_ + 768);
  __nv_bfloat16* Al  = Ah  + WMAT;
  __nv_bfloat16* B0h = Al  + WMAT;    // 4 contiguous matrix buffers follow
  __nv_bfloat16* B1h = B0h + 2*WMAT;
  const int t = threadIdx.x, w = t >> 5, l = t & 31;
  if (t < 128){
    sVec[t] = ub[t]; sVec[128 + t] = b2u[t];
    sVec[256 + t] = lg[t]; sVec[384 + t] = lb[t];
  }
  if (t < 256) sVec[512 + t] = g_gate[t];
  { const float4* s4 = (const float4*)(g_wsp + (size_t)(layer*5 + 2)*2*WMAT);
    float4* d4 = (float4*)B0h;
    for (int i = t; i < 4*WCPY; i += 256) d4[i] = s4[i]; }
  __syncthreads();
  const int m0 = w * 16;
  const int arow = (l & 7) + ((l >> 3) & 1)*8, acol = ((l >> 4) & 1)*8;
  const int brow = (l & 7) + ((l >> 4) & 1)*8, bcol = ((l >> 3) & 1)*8;
  const uint32_t uAh = smem_u32(Ah) + ((m0 + arow)*SPAD + acol)*2;
  const uint32_t uAl = smem_u32(Al) + ((m0 + arow)*SPAD + acol)*2;
  const uint32_t uB[2][2] = {
    { smem_u32(B0h) + (brow*SPAD + bcol)*2, smem_u32(B0h + WMAT) + (brow*SPAD + bcol)*2 },
    { smem_u32(B1h) + (brow*SPAD + bcol)*2, smem_u32(B1h + WMAT) + (brow*SPAD + bcol)*2 } };
  for (int tile = blockIdx.x; tile < NT_TILES; tile += gridDim.x){
    const int node0 = tile * TM;
    float acc[64];
    #pragma unroll
    for (int i = 0; i < 64; i++) acc[i] = 0.f;
    #pragma unroll
    for (int chunk = 0; chunk < 2; chunk++){
      stage_tile(chunk ? aggr : g_h, node0, Ah, Al,
                 chunk ? (const float*)nullptr : (sVec + 512), t);
      __syncthreads();
      #pragma unroll
      for (int ks = 0; ks < 8; ks++){
        const uint32_t ko = ks * 32;
        uint32_t a0,a1,a2,a3, e0,e1,e2,e3;
        LDSM4(a0,a1,a2,a3, uAh + ko);
        LDSM4(e0,e1,e2,e3, uAl + ko);
        #pragma unroll
        for (int nt2 = 0; nt2 < 8; nt2++){
          const uint32_t no = nt2 * (16*SPAD*2);
          uint32_t bh0,bh1,bh2,bh3, bl0,bl1,bl2,bl3;
          LDSM4(bh0,bh1,bh2,bh3, uB[chunk][0] + no + ko);
          LDSM4(bl0,bl1,bl2,bl3, uB[chunk][1] + no + ko);
          float* d0 = acc + (nt2*2+0)*4;
          float* d1 = acc + (nt2*2+1)*4;
          MMA16816(d0, a0,a1,a2,a3, bh0,bh1);
          MMA16816(d0, a0,a1,a2,a3, bl0,bl1);
          MMA16816(d0, e0,e1,e2,e3, bh0,bh1);
          MMA16816(d1, a0,a1,a2,a3, bh2,bh3);
          MMA16816(d1, a0,a1,a2,a3, bl2,bl3);
          MMA16816(d1, e0,e1,e2,e3, bh2,bh3);
        }
      }
      __syncthreads();
    }
    const int r0 = m0 + (l >> 2);
    const int n0v = node0 + r0, n1v = n0v + 8;
    const float dg0 = (n0v < BN) ? (float)g_deg[n0v % NN] : 0.f;
    const float dg1 = (n1v < BN) ? (float)g_deg[n1v % NN] : 0.f;
    const int gb0 = 512 + ((n0v < NN) ? 0 : DD);
    const int gb1 = 512 + ((n1v < NN) ? 0 : DD);
    float s0 = 0.f, q0 = 0.f, s1 = 0.f, q1 = 0.f;
    #pragma unroll
    for (int nt = 0; nt < 16; nt++){
      const int col = nt*8 + 2*(l & 3);
      float v0 = lrelu(acc[nt*4+0] + sVec[col]   + dg0*sVec[128+col]);
      float v1 = lrelu(acc[nt*4+1] + sVec[col+1] + dg0*sVec[129+col]);
      float v2 = lrelu(acc[nt*4+2] + sVec[col]   + dg1*sVec[128+col]);
      float v3 = lrelu(acc[nt*4+3] + sVec[col+1] + dg1*sVec[129+col]);
      acc[nt*4+0] = v0; acc[nt*4+1] = v1; acc[nt*4+2] = v2; acc[nt*4+3] = v3;
      s0 += v0 + v1; q0 += v0*v0 + v1*v1;
      s1 += v2 + v3; q1 += v2*v2 + v3*v3;
    }
    #pragma unroll
    for (int o = 1; o < 4; o <<= 1){
      s0 += __shfl_xor_sync(0xffffffffu, s0, o);
      q0 += __shfl_xor_sync(0xffffffffu, q0, o);
      s1 += __shfl_xor_sync(0xffffffffu, s1, o);
      q1 += __shfl_xor_sync(0xffffffffu, q1, o);
    }
    const float mu0 = s0 * (1.f/DD);
    const float rs0 = rsqrtf(q0*(1.f/DD) - mu0*mu0 + EPSF);
    const float mu1 = s1 * (1.f/DD);
    const float rs1 = rsqrtf(q1*(1.f/DD) - mu1*mu1 + EPSF);
    #pragma unroll
    for (int nt = 0; nt < 16; nt++){
      const int col = nt*8 + 2*(l & 3);
      if (n0v < BN){
        float2 h2 = *(float2*)(g_h + (size_t)n0v*DD + col);
        h2.x = h2.x*sVec[gb0+col]   + (acc[nt*4+0] - mu0)*rs0*sVec[256+col]   + sVec[384+col];
        h2.y = h2.y*sVec[gb0+col+1] + (acc[nt*4+1] - mu0)*rs0*sVec[257+col]   + sVec[385+col];
        *(float2*)(g_h + (size_t)n0v*DD + col) = h2;
      }
      if (n1v < BN){
        float2 h2 = *(float2*)(g_h + (size_t)n1v*DD + col);
        h2.x = h2.x*sVec[gb1+col]   + (acc[nt*4+2] - mu1)*rs1*sVec[256+col]   + sVec[384+col];
        h2.y = h2.y*sVec[gb1+col+1] + (acc[nt*4+3] - mu1)*rs1*sVec[257+col]   + sVec[385+col];
        *(float2*)(g_h + (size_t)n1v*DD + col) = h2;
      }
    }
    __syncthreads();
  }
}

// ======== HMMA gc + fused gate (last-block-done) =============================
__global__ __launch_bounds__(256,1) void k_gcm(
    const float* __restrict__ h, int layer, const float* __restrict__ ba,
    const float* __restrict__ Wb, const float* __restrict__ bb,
    const float* __restrict__ Wc, const float* __restrict__ bc){
  extern __shared__ __nv_bfloat16 sm_[];
  __nv_bfloat16* Ah = sm_;
  __nv_bfloat16* Al = Ah + WMAT;
  __nv_bfloat16* Bh = Al + WMAT;   // 2 contiguous matrix buffers
  float* sBa  = (float*)(Bh + 2*WMAT);   // 128
  float* sRed = sBa + 128;               // 2048
  __shared__ bool sLast;
  const int t = threadIdx.x, w = t >> 5, l = t & 31;
  { const float4* s4 = (const float4*)(g_wsp + (size_t)(layer*5 + 4)*2*WMAT);
    float4* d4 = (float4*)Bh;
    for (int i = t; i < 2*WCPY; i += 256) d4[i] = s4[i]; }
  if (t < 128) sBa[t] = ba[t];
  for (int i = t; i < 2048; i += 256) sRed[i] = 0.f;
  __syncthreads();
  const int m0 = w * 16;
  const int arow = (l & 7) + ((l >> 3) & 1)*8, acol = ((l >> 4) & 1)*8;
  const int brow = (l & 7) + ((l >> 4) & 1)*8, bcol = ((l >> 3) & 1)*8;
  const uint32_t uAh = smem_u32(Ah) + ((m0 + arow)*SPAD + acol)*2;
  const uint32_t uAl = smem_u32(Al) + ((m0 + arow)*SPAD + acol)*2;
  const uint32_t uBh = smem_u32(Bh) + (brow*SPAD + bcol)*2;
  const uint32_t uBl = smem_u32(Bh + WMAT) + (brow*SPAD + bcol)*2;
  for (int tile = blockIdx.x; tile < NT_TILES; tile += gridDim.x){
    const int node0 = tile * TM;
    stage_tile(h, node0, Ah, Al, (const float*)nullptr, t);
    __syncthreads();
    const int r0 = m0 + (l >> 2);
    const int n0v = node0 + r0, n1v = n0v + 8;
    const bool a0ok = n0v < NN;
    const bool a1ok = n1v < NN;
    const bool b0ok = (n0v >= NN) && (n0v < BN);
    const bool b1ok = (n1v >= NN) && (n1v < BN);
    #pragma unroll
    for (int half = 0; half < 2; half++){
      float acc[32];
      #pragma unroll
      for (int i = 0; i < 32; i++) acc[i] = 0.f;
      #pragma unroll
      for (int ks = 0; ks < 8; ks++){
        const uint32_t ko = ks * 32;
        uint32_t a0,a1,a2,a3, e0,e1,e2,e3;
        LDSM4(a0,a1,a2,a3, uAh + ko);
        LDSM4(e0,e1,e2,e3, uAl + ko);
        #pragma unroll
        for (int j = 0; j < 4; j++){
          const uint32_t no = (uint32_t)(half*4 + j) * (16*SPAD*2);
          uint32_t bh0,bh1,bh2,bh3, bl0,bl1,bl2,bl3;
          LDSM4(bh0,bh1,bh2,bh3, uBh + no + ko);
          LDSM4(bl0,bl1,bl2,bl3, uBl + no + ko);
          float* d0 = acc + j*8;
          float* d1 = acc + j*8 + 4;
          MMA16816(d0, a0,a1,a2,a3, bh0,bh1);
          MMA16816(d0, a0,a1,a2,a3, bl0,bl1);
          MMA16816(d0, e0,e1,e2,e3, bh0,bh1);
          MMA16816(d1, a0,a1,a2,a3, bh2,bh3);
          MMA16816(d1, a0,a1,a2,a3, bl2,bl3);
          MMA16816(d1, e0,e1,e2,e3, bh2,bh3);
        }
      }
      #pragma unroll
      for (int j = 0; j < 4; j++){
        #pragma unroll
        for (int sub = 0; sub < 2; sub++){
          const int base = j*8 + sub*4;
          const int col = half*64 + j*16 + sub*8 + 2*(l & 3);
          const float z00 = lrelu(acc[base+0] + sBa[col]);
          const float z01 = lrelu(acc[base+1] + sBa[col+1]);
          const float z10 = lrelu(acc[base+2] + sBa[col]);
          const float z11 = lrelu(acc[base+3] + sBa[col+1]);
          float v0a = (a0ok ? z00 : 0.f) + (a1ok ? z10 : 0.f);
          float v0b = (a0ok ? z01 : 0.f) + (a1ok ? z11 : 0.f);
          float v1a = (b0ok ? z00 : 0.f) + (b1ok ? z10 : 0.f);
          float v1b = (b0ok ? z01 : 0.f) + (b1ok ? z11 : 0.f);
          #pragma unroll
          for (int o = 4; o < 32; o <<= 1){
            v0a += __shfl_xor_sync(0xffffffffu, v0a, o);
            v0b += __shfl_xor_sync(0xffffffffu, v0b, o);
            v1a += __shfl_xor_sync(0xffffffffu, v1a, o);
            v1b += __shfl_xor_sync(0xffffffffu, v1b, o);
          }
          if ((l >> 2) == j*2 + sub){
            float* slot = sRed + w*256;
            slot[col]         += v0a;
            slot[col + 1]     += v0b;
            slot[128 + col]   += v1a;
            slot[128 + col+1] += v1b;
          }
        }
      }
    }
    __syncthreads();
  }
  if (t < 256){
    float s = 0.f;
    #pragma unroll
    for (int r = 0; r < 8; r++) s += sRed[r*256 + t];
    atomicAdd(&g_gs[t], s);
  }
  __threadfence();
  if (t == 0){
    int v = atomicAdd(&g_done, 1);
    sLast = (v == gridDim.x - 1);
  }
  __syncthreads();
  if (sLast){
    float* zm = sRed;
    float* s2 = sRed + 256;
    const int b = t >> 7, d = t & 127;
    zm[t] = g_gs[t] * (1.f/NN);
    g_gs[t] = 0.f;
    __syncthreads();
    float acc = bb[d];
    #pragma unroll 8
    for (int k = 0; k < DD; k++) acc += zm[b*DD + k] * Wb[k*DD + d];
    s2[t] = acc;
    __syncthreads();
    float acc2 = bc[d];
    #pragma unroll 8
    for (int k = 0; k < DD; k++) acc2 += s2[b*DD + k] * Wc[k*DD + d];
    g_gate[t] = 1.f/(1.f + expf(-acc2));
    if (t == 0) g_done = 0;
  }
}

// -------- CSR aggregation: both batches per warp, software prefetch ----------
__global__ void k_aggregate(const float* __restrict__ P, const float* __restrict__ Q,
                            const float* __restrict__ W1c, const float* __restrict__ b1,
                            const float* __restrict__ lg, const float* __restrict__ lb,
                            float* __restrict__ aggr){
  const int n = (blockIdx.x*blockDim.x + threadIdx.x) >> 5;
  if (n >= NN) return;
  const int lane = threadIdx.x & 31;
  const int off = g_row_off[n], end = g_row_off[n+1];
  const float4* Qv = (const float4*)Q;
  const float4 p0 = ((const float4*)(P + (size_t)n*DD))[lane];
  const float4 p1 = ((const float4*)(P + (size_t)(NN + n)*DD))[lane];
  const float4 w0 = ((const float4*)W1c)[lane];
  const float4 w1 = ((const float4*)(W1c + DD))[lane];
  const float4 bv = ((const float4*)b1)[lane];
  const float4 gv = ((const float4*)lg)[lane];
  const float4 bt = ((const float4*)lb)[lane];
  float4 acc0 = make_float4(0,0,0,0), acc1 = make_float4(0,0,0,0);
  int ncol = 0; float2 nea = make_float2(0,0);
  float4 qa = make_float4(0,0,0,0), qb = make_float4(0,0,0,0);
  if (off < end){
    ncol = g_csr_col[off]; nea = g_csr_ea[off];
    qa = Qv[(size_t)ncol*32 + lane];
    qb = Qv[(size_t)(NN + ncol)*32 + lane];
  }
  for (int i = off; i < end; i++){
    const float4 q0c = qa, q1c = qb; const float2 ec = nea;
    if (i + 1 < end){
      ncol = g_csr_col[i+1]; nea = g_csr_ea[i+1];
      qa = Qv[(size_t)ncol*32 + lane];
      qb = Qv[(size_t)(NN + ncol)*32 + lane];
    }
    const float ex0 = ec.x*w0.x + ec.y*w1.x + bv.x;
    const float ex1 = ec.x*w0.y + ec.y*w1.y + bv.y;
    const float ex2 = ec.x*w0.z + ec.y*w1.z + bv.z;
    const float ex3 = ec.x*w0.w + ec.y*w1.w + bv.w;
    const float a0 = lrelu(p0.x + q0c.x + ex0);
    const float a1 = lrelu(p0.y + q0c.y + ex1);
    const float a2 = lrelu(p0.z + q0c.z + ex2);
    const float a3 = lrelu(p0.w + q0c.w + ex3);
    const float b0 = lrelu(p1.x + q1c.x + ex0);
    const float b1x = lrelu(p1.y + q1c.y + ex1);
    const float b2 = lrelu(p1.z + q1c.z + ex2);
    const float b3 = lrelu(p1.w + q1c.w + ex3);
    float s0  = a0 + a1 + a2 + a3;
    float u0  = a0*a0 + a1*a1 + a2*a2 + a3*a3;
    float s1  = b0 + b1x + b2 + b3;
    float u1  = b0*b0 + b1x*b1x + b2*b2 + b3*b3;
    #pragma unroll
    for (int o = 16; o; o >>= 1){
      s0 += __shfl_xor_sync(0xffffffffu, s0, o);
      u0 += __shfl_xor_sync(0xffffffffu, u0, o);
      s1 += __shfl_xor_sync(0xffffffffu, s1, o);
      u1 += __shfl_xor_sync(0xffffffffu, u1, o);
    }
    const float mu0 = s0 * (1.f/DD);
    const float rs0 = rsqrtf(u0*(1.f/DD) - mu0*mu0 + EPSF);
    const float mu1 = s1 * (1.f/DD);
    const float rs1 = rsqrtf(u1*(1.f/DD) - mu1*mu1 + EPSF);
    acc0.x += (a0 - mu0)*rs0*gv.x + bt.x;
    acc0.y += (a1 - mu0)*rs0*gv.y + bt.y;
    acc0.z += (a2 - mu0)*rs0*gv.z + bt.z;
    acc0.w += (a3 - mu0)*rs0*gv.w + bt.w;
    acc1.x += (b0  - mu1)*rs1*gv.x + bt.x;
    acc1.y += (b1x - mu1)*rs1*gv.y + bt.y;
    acc1.z += (b2  - mu1)*rs1*gv.z + bt.z;
    acc1.w += (b3  - mu1)*rs1*gv.w + bt.w;
  }
  ((float4*)(aggr + (size_t)n*DD))[lane] = acc0;
  ((float4*)(aggr + (size_t)(NN + n)*DD))[lane] = acc1;
}

__device__ __forceinline__ void fma4(float4& acc, const float4 x,
                                     const float4 w0, const float4 w1,
                                     const float4 w2, const float4 w3){
  acc.x += x.x*w0.x + x.y*w1.x + x.z*w2.x + x.w*w3.x;
  acc.y += x.x*w0.y + x.y*w1.y + x.z*w2.y + x.w*w3.y;
  acc.z += x.x*w0.z + x.y*w1.z + x.z*w2.z + x.w*w3.z;
  acc.w += x.x*w0.w + x.y*w1.w + x.z*w2.w + x.w*w3.w;
}

// ---------------- decoder (applies final gate at read) -----------------------
__global__ __launch_bounds__(256,1) void k_dec(const float* __restrict__ W1,
    const float* __restrict__ b1, const float* __restrict__ W2,
    const float* __restrict__ b2, float* __restrict__ out){
  extern __shared__ float sm[];
  float* sW1 = sm;
  float* sIn = sm + DD*68;
  float* sU  = sIn + 32*DD;
  float* sW2 = sU + 32*64;
  float* sGate = sW2 + 130;
  const int t = threadIdx.x;
  const int dG = t & 15, nG = t >> 4;
  const int d0 = dG << 2;
  const int lane = t & 31, warp = t >> 5;
  for (int i = t; i < DD*64; i += 256){
    int k = i >> 6, d = i & 63;
    sW1[k*68 + d] = W1[i];
  }
  if (t < 128) sW2[t] = W2[t];
  if (t < 2) sW2[128 + t] = b2[t];
  if (t < 256) sGate[t] = g_gate[t];
  const float4 b1v = ((const float4*)b1)[dG];
  __syncthreads();
  for (int tile = blockIdx.x; tile < BN/32; tile += gridDim.x){
    const int node0 = tile * 32;
    for (int i = t; i < 32*DD/4; i += 256){
      const int node = node0 + (i >> 5), k4 = (i & 31) * 4;
      const int gb = (node < NN) ? 0 : DD;
      float4 v = ((const float4*)(g_h + (size_t)node*DD))[i & 31];
      v.x *= sGate[gb + k4]; v.y *= sGate[gb + k4 + 1];
      v.z *= sGate[gb + k4 + 2]; v.w *= sGate[gb + k4 + 3];
      ((float4*)sIn)[i] = v;
    }
    __syncthreads();
    float4 acc[2];
    acc[0] = make_float4(0,0,0,0); acc[1] = make_float4(0,0,0,0);
    #pragma unroll 4
    for (int k = 0; k < DD; k += 4){
      const float4 w0 = *(const float4*)(sW1 + (k+0)*68 + d0);
      const float4 w1 = *(const float4*)(sW1 + (k+1)*68 + d0);
      const float4 w2 = *(const float4*)(sW1 + (k+2)*68 + d0);
      const float4 w3 = *(const float4*)(sW1 + (k+3)*68 + d0);
      #pragma unroll
      for (int j = 0; j < 2; j++){
        const float4 x = *(const float4*)(sIn + ((nG<<1)+j)*DD + k);
        fma4(acc[j], x, w0, w1, w2, w3);
      }
    }
    #pragma unroll
    for (int j = 0; j < 2; j++){
      float4 v = acc[j];
      v.x = lrelu(v.x + b1v.x); v.y = lrelu(v.y + b1v.y);
      v.z = lrelu(v.z + b1v.z); v.w = lrelu(v.w + b1v.w);
      *(float4*)(sU + ((nG<<1)+j)*64 + d0) = v;
    }
    __syncthreads();
    #pragma unroll
    for (int j = 0; j < 4; j++){
      const int nl = (warp<<2) + j;
      const float u0 = sU[nl*64 + lane];
      const float u1 = sU[nl*64 + lane + 32];
      float o0 = u0*sW2[lane*2]   + u1*sW2[(lane+32)*2];
      float o1 = u0*sW2[lane*2+1] + u1*sW2[(lane+32)*2+1];
      #pragma unroll
      for (int o = 16; o; o >>= 1){
        o0 += __shfl_xor_sync(0xffffffffu, o0, o);
        o1 += __shfl_xor_sync(0xffffffffu, o1, o);
      }
      if (lane == 0){
        out[(size_t)(node0 + nl)*2]     = o0 + sW2[128];
        out[(size_t)(node0 + nl)*2 + 1] = o1 + sW2[129];
      }
    }
    __syncthreads();
  }
}

// ---------------- host -------------------------------------------------------
extern "C" void kernel_launch(void* const* d_in, const int* in_sizes, int n_in,
                              void* d_out, int out_size){
  const float* x      = (const float*)d_in[0];
  const float* ea     = (const float*)d_in[1];
  const int*   ei     = (const int*)  d_in[2];
  const float* enc_W  = (const float*)d_in[3];
  const float* enc_b  = (const float*)d_in[4];
  const float* msg_W1 = (const float*)d_in[5];
  const float* msg_b1 = (const float*)d_in[6];
  const float* msg_lg = (const float*)d_in[7];
  const float* msg_lb = (const float*)d_in[8];
  const float* msg_W2 = (const float*)d_in[9];
  const float* msg_b2 = (const float*)d_in[10];
  const float* up_W   = (const float*)d_in[11];
  const float* up_b   = (const float*)d_in[12];
  const float* up_lg  = (const float*)d_in[13];
  const float* up_lb  = (const float*)d_in[14];
  const float* gc_Wa  = (const float*)d_in[15];
  const float* gc_ba  = (const float*)d_in[16];
  const float* gc_Wb  = (const float*)d_in[17];
  const float* gc_bb  = (const float*)d_in[18];
  const float* gc_Wc  = (const float*)d_in[19];
  const float* gc_bc  = (const float*)d_in[20];
  const float* dec_W1 = (const float*)d_in[21];
  const float* dec_b1 = (const float*)d_in[22];
  const float* dec_W2 = (const float*)d_in[23];
  const float* dec_b2 = (const float*)d_in[24];
  float* out = (float*)d_out;

  void *p_h, *p_P, *p_Q, *p_aggr, *p_deg, *p_b2u;
  cudaGetSymbolAddress(&p_h, g_h);
  cudaGetSymbolAddress(&p_P, g_P);
  cudaGetSymbolAddress(&p_Q, g_Q);
  cudaGetSymbolAddress(&p_aggr, g_aggr);
  cudaGetSymbolAddress(&p_deg, g_deg);
  cudaGetSymbolAddress(&p_b2u, g_b2u);

  const int SM_MPQ = 6*WMAT*2;                            // 208896
  const int SM_MUP = 768*4 + 6*WMAT*2;                    // 211968
  const int SM_GCM = 4*WMAT*2 + (128 + 2048)*4;           // 147968
  const int SM_DEC = (DD*68 + 32*DD + 32*64 + 130 + 256) * 4;
  cudaFuncSetAttribute(k_mmaPQ, cudaFuncAttributeMaxDynamicSharedMemorySize, SM_MPQ);
  cudaFuncSetAttribute(k_mmaUP, cudaFuncAttributeMaxDynamicSharedMemorySize, SM_MUP);
  cudaFuncSetAttribute(k_gcm,   cudaFuncAttributeMaxDynamicSharedMemorySize, SM_GCM);
  cudaFuncSetAttribute(k_dec,   cudaFuncAttributeMaxDynamicSharedMemorySize, SM_DEC);

  cudaMemsetAsync(p_deg, 0, NN*sizeof(int), 0);
  k_encoder<<<BN, DD>>>(x, enc_W, enc_b);
  k_ginit<<<1, 256>>>();
  k_deg<<<(EE + 255)/256, 256>>>(ei);
  k_scan<<<1, 1024>>>();
  k_scatter<<<(EE + 255)/256, 256>>>(ei, ea);
  { dim3 g(NLAYERS, DD+1); k_prew2<<<g, DD>>>(msg_W2, msg_b2, up_W); }
  { dim3 g(NLAYERS, 5); k_presplit<<<g, 256>>>(msg_W1, up_W, gc_Wa); }

  for (int l = 0; l < NLAYERS; l++){
    const float* W1c = msg_W1 + (size_t)l*258*DD + (size_t)256*DD;
    const float* b1  = msg_b1 + l*DD;
    const float* mlg = msg_lg + l*DD;
    const float* mlb = msg_lb + l*DD;
    const float* ubl = up_b  + l*DD;
    const float* ulg = up_lg + l*DD;
    const float* ulb = up_lb + l*DD;
    const float* ba  = gc_ba + l*DD;
    const float* Wb  = gc_Wb + (size_t)l*DD*DD;
    const float* bbv = gc_bb + l*DD;
    const float* Wc  = gc_Wc + (size_t)l*DD*DD;
    const float* bc  = gc_bc + l*DD;
    const float* b2u = (const float*)p_b2u + (size_t)l*DD;

    k_mmaPQ<<<148, 256, SM_MPQ>>>((const float*)p_h, l, (float*)p_P, (float*)p_Q);
    k_aggregate<<<(NN + 7)/8, 256>>>((const float*)p_P, (const float*)p_Q,
                                     W1c, b1, mlg, mlb, (float*)p_aggr);
    k_mmaUP<<<148, 256, SM_MUP>>>((const float*)p_aggr, l, b2u, ubl, ulg, ulb);
    k_gcm<<<148, 256, SM_GCM>>>((const float*)p_h, l, ba, Wb, bbv, Wc, bc);
  }

  k_dec<<<148, 256, SM_DEC>>>(dec_W1, dec_b1, dec_W2, dec_b2, out);
}